// round 1
// baseline (speedup 1.0000x reference)
#include <cuda_runtime.h>
#include <cuda_bf16.h>
#include <cstdint>

#define N_NODES 50000
#define N_EDGES 800000
#define NFEAT   512
#define NHID    64
#define NHEAD   8
#define F1      512      // NHEAD*NHID
#define NCLASS  40
#define NEG     0.2f

// ---------------- scratch (static device allocations; no runtime alloc) ----
__device__ float g_h1[(size_t)N_NODES * F1];     // layer-1 per-head features [N, h*64+c]
__device__ float g_z [(size_t)N_NODES * F1];     // elu(agg1 + b1)  (layer-2 input)
__device__ float g_h2[(size_t)N_NODES * NCLASS]; // layer-2 linear output
__device__ float g_s1s[N_NODES * NHEAD];
__device__ float g_s1d[N_NODES * NHEAD];
__device__ float g_s2s[N_NODES];
__device__ float g_s2d[N_NODES];
__device__ int   g_deg[N_NODES];
__device__ int   g_off[N_NODES + 1];
__device__ int   g_cur[N_NODES];
__device__ int   g_csr_src[N_EDGES];
__device__ float g_Wt[NFEAT * F1];               // W1 repacked: [k, h*64+c]

// ---------------- CSR construction ----------------------------------------
__global__ void k_zero_deg() {
    int i = blockIdx.x * blockDim.x + threadIdx.x;
    if (i < N_NODES) g_deg[i] = 0;
}

__global__ void k_count(const int* __restrict__ dst) {
    int e = blockIdx.x * blockDim.x + threadIdx.x;
    if (e < N_EDGES) atomicAdd(&g_deg[dst[e]], 1);
}

__global__ void k_scan() {
    __shared__ int sh[1024];
    __shared__ int run;
    int t = threadIdx.x;
    if (t == 0) run = 0;
    __syncthreads();
    for (int base = 0; base < N_NODES; base += 1024) {
        int i = base + t;
        int v = (i < N_NODES) ? g_deg[i] : 0;
        sh[t] = v;
        __syncthreads();
        int x = v;
        for (int off = 1; off < 1024; off <<= 1) {
            int y = (t >= off) ? sh[t - off] : 0;
            __syncthreads();
            x += y;
            sh[t] = x;
            __syncthreads();
        }
        int r = run;
        if (i < N_NODES) {
            int excl = r + x - v;
            g_off[i] = excl;
            g_cur[i] = excl;
        }
        __syncthreads();
        if (t == 1023) run = r + x;
        __syncthreads();
    }
    if (t == 0) g_off[N_NODES] = N_EDGES;
}

__global__ void k_fill(const int* __restrict__ src, const int* __restrict__ dst) {
    int e = blockIdx.x * blockDim.x + threadIdx.x;
    if (e < N_EDGES) {
        int d = dst[e];
        int p = atomicAdd(&g_cur[d], 1);
        g_csr_src[p] = src[e];
    }
}

// ---------------- W1 repack: Wt[k, h*64+c] = W1[h, k, c] --------------------
__global__ void k_wt(const float* __restrict__ W1) {
    int idx = blockIdx.x * blockDim.x + threadIdx.x;
    if (idx < NFEAT * F1) {
        int k   = idx / F1;
        int col = idx - k * F1;
        int h   = col >> 6;
        int c   = col & 63;
        g_Wt[idx] = W1[((size_t)h * NFEAT + k) * NHID + c];
    }
}

// ---------------- GEMM1: h1 = x[50000,512] @ Wt[512,512] -------------------
// Tile 128x64, BK=16, 256 threads, 8x4 per-thread microtile.
__global__ __launch_bounds__(256) void k_gemm1(const float* __restrict__ A) {
    __shared__ float As[16 * 132];
    __shared__ float Bs[16 * 68];
    const int bm = blockIdx.x * 128;
    const int bn = blockIdx.y * 64;
    const int t  = threadIdx.x;
    const int tx = t & 15;   // N dir
    const int ty = t >> 4;   // M dir

    float acc[8][4];
#pragma unroll
    for (int i = 0; i < 8; i++)
#pragma unroll
        for (int j = 0; j < 4; j++) acc[i][j] = 0.f;

    for (int k0 = 0; k0 < NFEAT; k0 += 16) {
        // A tile: 128x16 = 512 float4
#pragma unroll
        for (int it = 0; it < 2; it++) {
            int q  = t + 256 * it;
            int m  = q >> 2;
            int k4 = (q & 3) * 4;
            int row = bm + m;
            float4 v = make_float4(0.f, 0.f, 0.f, 0.f);
            if (row < N_NODES)
                v = *(const float4*)(A + (size_t)row * NFEAT + k0 + k4);
            As[(k4 + 0) * 132 + m] = v.x;
            As[(k4 + 1) * 132 + m] = v.y;
            As[(k4 + 2) * 132 + m] = v.z;
            As[(k4 + 3) * 132 + m] = v.w;
        }
        // B tile: 16x64 = 256 float4
        {
            int n4 = t & 15;
            int kk = t >> 4;
            float4 v = *(const float4*)(g_Wt + (size_t)(k0 + kk) * F1 + bn + n4 * 4);
            *(float4*)&Bs[kk * 68 + n4 * 4] = v;
        }
        __syncthreads();
#pragma unroll
        for (int kk = 0; kk < 16; kk++) {
            float4 a0 = *(const float4*)&As[kk * 132 + ty * 8];
            float4 a1 = *(const float4*)&As[kk * 132 + ty * 8 + 4];
            float4 b  = *(const float4*)&Bs[kk * 68 + tx * 4];
            float av[8] = {a0.x, a0.y, a0.z, a0.w, a1.x, a1.y, a1.z, a1.w};
            float bv[4] = {b.x, b.y, b.z, b.w};
#pragma unroll
            for (int i = 0; i < 8; i++)
#pragma unroll
                for (int j = 0; j < 4; j++) acc[i][j] += av[i] * bv[j];
        }
        __syncthreads();
    }
#pragma unroll
    for (int i = 0; i < 8; i++) {
        int row = bm + ty * 8 + i;
        if (row < N_NODES) {
            float4 v = make_float4(acc[i][0], acc[i][1], acc[i][2], acc[i][3]);
            *(float4*)(g_h1 + (size_t)row * F1 + bn + tx * 4) = v;
        }
    }
}

// ---------------- per-node attention scores, layer 1 -----------------------
// warp per node; lane handles 16 features; head = lane/4.
__global__ void k_scores1(const float* __restrict__ a1) {
    int gw   = (blockIdx.x * blockDim.x + threadIdx.x) >> 5;
    int lane = threadIdx.x & 31;
    if (gw >= N_NODES) return;
    int h  = lane >> 2;
    int cl = (lane & 3) * 16;
    const float4* hp = (const float4*)(g_h1 + (size_t)gw * F1 + lane * 16);
    const float*  as = a1 + h * 128 + cl;
    const float*  ad = a1 + h * 128 + 64 + cl;
    float ss = 0.f, sd = 0.f;
#pragma unroll
    for (int j = 0; j < 4; j++) {
        float4 v = hp[j];
        ss += v.x * as[j * 4 + 0] + v.y * as[j * 4 + 1] + v.z * as[j * 4 + 2] + v.w * as[j * 4 + 3];
        sd += v.x * ad[j * 4 + 0] + v.y * ad[j * 4 + 1] + v.z * ad[j * 4 + 2] + v.w * ad[j * 4 + 3];
    }
    ss += __shfl_xor_sync(0xffffffffu, ss, 1);
    ss += __shfl_xor_sync(0xffffffffu, ss, 2);
    sd += __shfl_xor_sync(0xffffffffu, sd, 1);
    sd += __shfl_xor_sync(0xffffffffu, sd, 2);
    if ((lane & 3) == 0) {
        g_s1s[gw * NHEAD + h] = ss;
        g_s1d[gw * NHEAD + h] = sd;
    }
}

__device__ __forceinline__ float lrelu(float x) { return x > 0.f ? x : NEG * x; }

// ---------------- layer-1 softmax-aggregate --------------------------------
// warp per dst node. Lanes: (edge-slot es = lane/8) x (head h = lane%8) for
// max/sum passes; feature lanes (16 feats each, head = lane/4) for aggregation.
__global__ __launch_bounds__(256) void k_agg1(const float* __restrict__ b1) {
    int n    = (blockIdx.x * blockDim.x + threadIdx.x) >> 5;
    int lane = threadIdx.x & 31;
    if (n >= N_NODES) return;
    const int beg = g_off[n], end = g_off[n + 1];

    const int h  = lane & 7;
    const int es = lane >> 3;
    const float sdh = g_s1d[n * NHEAD + h];

    // pass 1: per-head max
    float m = -1e30f;
    for (int i = beg + es; i < end; i += 4) {
        int s = g_csr_src[i];
        float e = lrelu(g_s1s[s * NHEAD + h] + sdh);
        m = fmaxf(m, e);
    }
    m = fmaxf(m, __shfl_xor_sync(0xffffffffu, m, 8));
    m = fmaxf(m, __shfl_xor_sync(0xffffffffu, m, 16));

    // pass 2: per-head denom
    float den = 0.f;
    for (int i = beg + es; i < end; i += 4) {
        int s = g_csr_src[i];
        float e = lrelu(g_s1s[s * NHEAD + h] + sdh);
        den += __expf(e - m);
    }
    den += __shfl_xor_sync(0xffffffffu, den, 8);
    den += __shfl_xor_sync(0xffffffffu, den, 16);
    den = fmaxf(den, 1e-16f);

    // pass 3: weighted feature aggregation (16 features/lane)
    float acc[16];
#pragma unroll
    for (int j = 0; j < 16; j++) acc[j] = 0.f;
    const int hl = lane >> 2;  // head of this lane's features

    for (int i = beg; i < end; i++) {
        int s = g_csr_src[i];
        float alpha = 0.f;
        if (lane < 8) {
            float e = lrelu(g_s1s[s * NHEAD + lane] + sdh);
            alpha = __expf(e - m) / den;
        }
        alpha = __shfl_sync(0xffffffffu, alpha, hl);
        const float4* hp = (const float4*)(g_h1 + (size_t)s * F1 + lane * 16);
#pragma unroll
        for (int j = 0; j < 4; j++) {
            float4 v = hp[j];
            acc[j * 4 + 0] += alpha * v.x;
            acc[j * 4 + 1] += alpha * v.y;
            acc[j * 4 + 2] += alpha * v.z;
            acc[j * 4 + 3] += alpha * v.w;
        }
    }

    // epilogue: + bias, ELU, store
    const float4* bp = (const float4*)(b1 + lane * 16);
    float4* zp = (float4*)(g_z + (size_t)n * F1 + lane * 16);
#pragma unroll
    for (int j = 0; j < 4; j++) {
        float4 b = bp[j];
        float v0 = acc[j * 4 + 0] + b.x;
        float v1 = acc[j * 4 + 1] + b.y;
        float v2 = acc[j * 4 + 2] + b.z;
        float v3 = acc[j * 4 + 3] + b.w;
        v0 = v0 > 0.f ? v0 : expm1f(v0);
        v1 = v1 > 0.f ? v1 : expm1f(v1);
        v2 = v2 > 0.f ? v2 : expm1f(v2);
        v3 = v3 > 0.f ? v3 : expm1f(v3);
        zp[j] = make_float4(v0, v1, v2, v3);
    }
}

// ---------------- GEMM2: h2 = z[50000,512] @ W2[512,40] --------------------
// Tile 128x40, BK=16, 256 threads (tx=t%8 -> 5 cols, ty=t/8 -> 4 rows).
__global__ __launch_bounds__(256) void k_gemm2(const float* __restrict__ W2) {
    __shared__ float As[16 * 132];
    __shared__ float Bs[16 * 44];
    const int bm = blockIdx.x * 128;
    const int t  = threadIdx.x;
    const int tx = t & 7;
    const int ty = t >> 3;

    float acc[4][5];
#pragma unroll
    for (int i = 0; i < 4; i++)
#pragma unroll
        for (int j = 0; j < 5; j++) acc[i][j] = 0.f;

    for (int k0 = 0; k0 < F1; k0 += 16) {
#pragma unroll
        for (int it = 0; it < 2; it++) {
            int q  = t + 256 * it;
            int m  = q >> 2;
            int k4 = (q & 3) * 4;
            int row = bm + m;
            float4 v = make_float4(0.f, 0.f, 0.f, 0.f);
            if (row < N_NODES)
                v = *(const float4*)(g_z + (size_t)row * F1 + k0 + k4);
            As[(k4 + 0) * 132 + m] = v.x;
            As[(k4 + 1) * 132 + m] = v.y;
            As[(k4 + 2) * 132 + m] = v.z;
            As[(k4 + 3) * 132 + m] = v.w;
        }
        for (int q = t; q < 16 * NCLASS; q += 256) {
            int kk = q / NCLASS;
            int c  = q - kk * NCLASS;
            Bs[kk * 44 + c] = W2[(size_t)(k0 + kk) * NCLASS + c];
        }
        __syncthreads();
#pragma unroll
        for (int kk = 0; kk < 16; kk++) {
            float4 av = *(const float4*)&As[kk * 132 + ty * 4];
            float a[4] = {av.x, av.y, av.z, av.w};
            float b[5];
#pragma unroll
            for (int j = 0; j < 5; j++) b[j] = Bs[kk * 44 + tx * 5 + j];
#pragma unroll
            for (int i = 0; i < 4; i++)
#pragma unroll
                for (int j = 0; j < 5; j++) acc[i][j] += a[i] * b[j];
        }
        __syncthreads();
    }
#pragma unroll
    for (int i = 0; i < 4; i++) {
        int row = bm + ty * 4 + i;
        if (row < N_NODES) {
#pragma unroll
            for (int j = 0; j < 5; j++)
                g_h2[(size_t)row * NCLASS + tx * 5 + j] = acc[i][j];
        }
    }
}

// ---------------- per-node attention scores, layer 2 -----------------------
__global__ void k_scores2(const float* __restrict__ a2) {
    int gw   = (blockIdx.x * blockDim.x + threadIdx.x) >> 5;
    int lane = threadIdx.x & 31;
    if (gw >= N_NODES) return;
    float v0 = g_h2[(size_t)gw * NCLASS + lane];
    float ss = v0 * a2[lane];
    float sd = v0 * a2[NCLASS + lane];
    if (lane < 8) {
        float v1 = g_h2[(size_t)gw * NCLASS + 32 + lane];
        ss += v1 * a2[32 + lane];
        sd += v1 * a2[NCLASS + 32 + lane];
    }
#pragma unroll
    for (int off = 16; off > 0; off >>= 1) {
        ss += __shfl_xor_sync(0xffffffffu, ss, off);
        sd += __shfl_xor_sync(0xffffffffu, sd, off);
    }
    if (lane == 0) {
        g_s2s[gw] = ss;
        g_s2d[gw] = sd;
    }
}

// ---------------- layer-2 aggregate + bias + log_softmax -------------------
__global__ __launch_bounds__(256) void k_agg2(const float* __restrict__ b2,
                                              float* __restrict__ out) {
    int n    = (blockIdx.x * blockDim.x + threadIdx.x) >> 5;
    int lane = threadIdx.x & 31;
    if (n >= N_NODES) return;
    const int beg = g_off[n], end = g_off[n + 1];
    const float sdn = g_s2d[n];

    // pass 1: max
    float m = -1e30f;
    for (int i = beg + lane; i < end; i += 32) {
        int s = g_csr_src[i];
        m = fmaxf(m, lrelu(g_s2s[s] + sdn));
    }
#pragma unroll
    for (int off = 16; off > 0; off >>= 1)
        m = fmaxf(m, __shfl_xor_sync(0xffffffffu, m, off));

    // pass 2: denom
    float den = 0.f;
    for (int i = beg + lane; i < end; i += 32) {
        int s = g_csr_src[i];
        den += __expf(lrelu(g_s2s[s] + sdn) - m);
    }
#pragma unroll
    for (int off = 16; off > 0; off >>= 1)
        den += __shfl_xor_sync(0xffffffffu, den, off);
    den = fmaxf(den, 1e-16f);

    // pass 3: aggregate (c = lane, and c = 32+lane for lane<8)
    float acc0 = 0.f, acc1 = 0.f;
    for (int i = beg; i < end; i++) {
        int s = g_csr_src[i];
        float e = lrelu(g_s2s[s] + sdn);
        float alpha = __expf(e - m) / den;
        acc0 += alpha * g_h2[(size_t)s * NCLASS + lane];
        if (lane < 8) acc1 += alpha * g_h2[(size_t)s * NCLASS + 32 + lane];
    }

    float v0 = acc0 + b2[lane];
    float v1 = (lane < 8) ? (acc1 + b2[32 + lane]) : -1e30f;

    // log_softmax over 40 classes within the warp
    float mx = fmaxf(v0, v1);
#pragma unroll
    for (int off = 16; off > 0; off >>= 1)
        mx = fmaxf(mx, __shfl_xor_sync(0xffffffffu, mx, off));
    float se = __expf(v0 - mx) + ((lane < 8) ? __expf(v1 - mx) : 0.f);
#pragma unroll
    for (int off = 16; off > 0; off >>= 1)
        se += __shfl_xor_sync(0xffffffffu, se, off);
    float ls = logf(se);

    out[(size_t)n * NCLASS + lane] = v0 - mx - ls;
    if (lane < 8) out[(size_t)n * NCLASS + 32 + lane] = v1 - mx - ls;
}

// ---------------- launch ----------------------------------------------------
extern "C" void kernel_launch(void* const* d_in, const int* in_sizes, int n_in,
                              void* d_out, int out_size) {
    const float* x  = (const float*)d_in[0];
    const int*   el = (const int*)d_in[1];
    const float* W1 = (const float*)d_in[2];
    const float* a1 = (const float*)d_in[3];
    const float* b1 = (const float*)d_in[4];
    const float* W2 = (const float*)d_in[5];
    const float* a2 = (const float*)d_in[6];
    const float* b2 = (const float*)d_in[7];
    float* out = (float*)d_out;

    const int* src = el;
    const int* dst = el + N_EDGES;

    const int TB = 256;
    k_zero_deg<<<(N_NODES + TB - 1) / TB, TB>>>();
    k_count<<<(N_EDGES + TB - 1) / TB, TB>>>(dst);
    k_scan<<<1, 1024>>>();
    k_fill<<<(N_EDGES + TB - 1) / TB, TB>>>(src, dst);
    k_wt<<<(NFEAT * F1 + TB - 1) / TB, TB>>>(W1);

    k_gemm1<<<dim3((N_NODES + 127) / 128, F1 / 64), 256>>>(x);
    k_scores1<<<(N_NODES + 7) / 8, 256>>>(a1);
    k_agg1<<<(N_NODES + 7) / 8, 256>>>(b1);

    k_gemm2<<<(N_NODES + 127) / 128, 256>>>(W2);
    k_scores2<<<(N_NODES + 7) / 8, 256>>>(a2);
    k_agg2<<<(N_NODES + 7) / 8, 256>>>(b2, out);
}

// round 3
// speedup vs baseline: 1.2495x; 1.2495x over previous
#include <cuda_runtime.h>
#include <cuda_bf16.h>
#include <cstdint>

#define N_NODES 50000
#define N_EDGES 800000
#define NFEAT   512
#define NHID    64
#define NHEAD   8
#define F1      512      // NHEAD*NHID
#define NCLASS  40
#define NEG     0.2f

// ---------------- scratch ---------------------------------------------------
__device__ float g_h1[(size_t)N_NODES * F1];
__device__ float g_z [(size_t)N_NODES * F1];
__device__ float g_h2[(size_t)N_NODES * NCLASS];
__device__ float g_s1s[N_NODES * NHEAD];
__device__ float g_s1d[N_NODES * NHEAD];
__device__ float g_s2s[N_NODES];
__device__ float g_s2d[N_NODES];
__device__ int   g_deg[N_NODES];
__device__ int   g_off[N_NODES + 1];
__device__ int   g_cur[N_NODES];
__device__ int   g_csr_src[N_EDGES];
// bf16 split operands for the mma.sync GEMM1
__device__ __nv_bfloat16 g_xhi[(size_t)N_NODES * NFEAT];
__device__ __nv_bfloat16 g_xlo[(size_t)N_NODES * NFEAT];
__device__ __nv_bfloat16 g_WThi[F1 * NFEAT];   // [n][k], n = h*64+c
__device__ __nv_bfloat16 g_WTlo[F1 * NFEAT];

__device__ __forceinline__ uint32_t smem_u32(const void* p) {
    uint32_t a;
    asm("{ .reg .u64 t; cvta.to.shared.u64 t, %1; cvt.u32.u64 %0, t; }" : "=r"(a) : "l"(p));
    return a;
}

// ---------------- CSR construction ------------------------------------------
__global__ void k_zero_deg() {
    int i = blockIdx.x * blockDim.x + threadIdx.x;
    if (i < N_NODES) g_deg[i] = 0;
}
__global__ void k_count(const int* __restrict__ dst) {
    int e = blockIdx.x * blockDim.x + threadIdx.x;
    if (e < N_EDGES) atomicAdd(&g_deg[dst[e]], 1);
}
__global__ void k_scan() {
    __shared__ int sh[1024];
    __shared__ int run;
    int t = threadIdx.x;
    if (t == 0) run = 0;
    __syncthreads();
    for (int base = 0; base < N_NODES; base += 1024) {
        int i = base + t;
        int v = (i < N_NODES) ? g_deg[i] : 0;
        sh[t] = v;
        __syncthreads();
        int x = v;
        for (int off = 1; off < 1024; off <<= 1) {
            int y = (t >= off) ? sh[t - off] : 0;
            __syncthreads();
            x += y;
            sh[t] = x;
            __syncthreads();
        }
        int r = run;
        if (i < N_NODES) {
            int excl = r + x - v;
            g_off[i] = excl;
            g_cur[i] = excl;
        }
        __syncthreads();
        if (t == 1023) run = r + x;
        __syncthreads();
    }
    if (t == 0) g_off[N_NODES] = N_EDGES;
}
__global__ void k_fill(const int* __restrict__ src, const int* __restrict__ dst) {
    int e = blockIdx.x * blockDim.x + threadIdx.x;
    if (e < N_EDGES) {
        int d = dst[e];
        int p = atomicAdd(&g_cur[d], 1);
        g_csr_src[p] = src[e];
    }
}

// ---------------- bf16 splits ------------------------------------------------
__global__ void k_split_x(const float* __restrict__ x) {
    int i = blockIdx.x * blockDim.x + threadIdx.x;      // one per 8 elems
    const int total = N_NODES * NFEAT / 8;
    if (i >= total) return;
    const float4* p = (const float4*)x + (size_t)i * 2;
    float4 v0 = p[0], v1 = p[1];
    float f[8] = {v0.x, v0.y, v0.z, v0.w, v1.x, v1.y, v1.z, v1.w};
    __nv_bfloat16 hi[8], lo[8];
#pragma unroll
    for (int j = 0; j < 8; j++) {
        hi[j] = __float2bfloat16(f[j]);
        lo[j] = __float2bfloat16(f[j] - __bfloat162float(hi[j]));
    }
    *(uint4*)(g_xhi + (size_t)i * 8) = *(uint4*)hi;
    *(uint4*)(g_xlo + (size_t)i * 8) = *(uint4*)lo;
}
__global__ void k_split_w(const float* __restrict__ W1) {
    int idx = blockIdx.x * blockDim.x + threadIdx.x;
    if (idx >= F1 * NFEAT) return;
    int n = idx >> 9, k = idx & 511;
    int h = n >> 6, c = n & 63;
    float w = W1[((size_t)h * NFEAT + k) * NHID + c];
    __nv_bfloat16 hi = __float2bfloat16(w);
    __nv_bfloat16 lo = __float2bfloat16(w - __bfloat162float(hi));
    g_WThi[(size_t)n * NFEAT + k] = hi;
    g_WTlo[(size_t)n * NFEAT + k] = lo;
}

// ---------------- GEMM1 (mma.sync bf16): h1 = x @ Wt, 3-term split ----------
// C[50000,512] = A''[50000,1536] * B''[1536,512]
//   A'' K-sectors: [x_hi | x_lo | x_hi],  B'' K-sectors: [W_hi ; W_hi ; W_lo]
// CTA tile 128x256, BK=32, 8 warps (2m x 4n), warp tile 64x64.
#define G1_BM      128
#define G1_BN      256
#define G1_BK      32
#define G1_KITER   48                // 1536 / 32
#define G1_ROWH    40                // padded row: 32 halves + 8 pad
#define G1_ROWB    80                // bytes
#define G1_ASZ     (G1_BM * G1_ROWB) // 10240
#define G1_BSZ     (G1_BN * G1_ROWB) // 20480
#define G1_STAGE   (G1_ASZ + G1_BSZ) // 30720
#define G1_SMEM    (2 * G1_STAGE)    // 61440

__device__ __forceinline__ void g1_prefetch(int kb, uint32_t stage, int bm, int bn, int t) {
    const int sector = kb >> 4;
    const int k_in   = (kb & 15) * G1_BK;
    const __nv_bfloat16* Asrc = (sector == 1) ? g_xlo  : g_xhi;
    const __nv_bfloat16* Bsrc = (sector == 2) ? g_WTlo : g_WThi;
#pragma unroll
    for (int i = 0; i < 6; i++) {
        int q = t + i * 256;
        if (q < 512) {                       // A: 128 rows x 4 chunks
            int row = q >> 2, c = q & 3;
            int grow = bm + row;
            int ok = grow < N_NODES;
            if (!ok) grow = 0;
            uint32_t dst = stage + row * G1_ROWB + c * 16;
            const void* srcp = Asrc + (size_t)grow * NFEAT + k_in + c * 8;
            int sz = ok ? 16 : 0;
            asm volatile("cp.async.cg.shared.global [%0], [%1], 16, %2;"
                         :: "r"(dst), "l"(srcp), "r"(sz));
        } else {                             // B: 256 rows x 4 chunks
            int qb = q - 512;
            int row = qb >> 2, c = qb & 3;
            uint32_t dst = stage + G1_ASZ + row * G1_ROWB + c * 16;
            const void* srcp = Bsrc + (size_t)(bn + row) * NFEAT + k_in + c * 8;
            asm volatile("cp.async.cg.shared.global [%0], [%1], 16;"
                         :: "r"(dst), "l"(srcp));
        }
    }
}

__global__ __launch_bounds__(256, 1) void k_gemm1_mma() {
    extern __shared__ char dyn[];
    const uint32_t sbase = smem_u32(dyn);
    const int t    = threadIdx.x;
    const int wid  = t >> 5;
    const int lane = t & 31;
    const int bm   = blockIdx.x * G1_BM;
    const int bn   = blockIdx.y * G1_BN;
    const int mw   = (wid >> 2) * 64;        // warp m offset in CTA
    const int nw   = (wid & 3) * 64;         // warp n offset in CTA

    float acc[4][8][4];
#pragma unroll
    for (int mt = 0; mt < 4; mt++)
#pragma unroll
        for (int nt = 0; nt < 8; nt++)
#pragma unroll
            for (int j = 0; j < 4; j++) acc[mt][nt][j] = 0.f;

    g1_prefetch(0, sbase, bm, bn, t);
    asm volatile("cp.async.commit_group;");
    g1_prefetch(1, sbase + G1_STAGE, bm, bn, t);
    asm volatile("cp.async.commit_group;");

    // ldmatrix source offsets (within a stage)
    const uint32_t a_off = (mw + (lane & 15)) * G1_ROWB + ((lane >> 4) * 16);
    const uint32_t b_off = G1_ASZ +
        (nw + (lane & 7) + ((lane >> 4) << 3)) * G1_ROWB + (((lane >> 3) & 1) * 16);

    for (int kb = 0; kb < G1_KITER; kb++) {
        asm volatile("cp.async.wait_group 1;");
        __syncthreads();
        const uint32_t stage = sbase + (kb & 1) * G1_STAGE;

#pragma unroll
        for (int ks = 0; ks < 2; ks++) {
            uint32_t a[4][4];
#pragma unroll
            for (int mt = 0; mt < 4; mt++) {
                uint32_t addr = stage + a_off + mt * (16 * G1_ROWB) + ks * 32;
                asm volatile("ldmatrix.sync.aligned.m8n8.x4.shared.b16 {%0,%1,%2,%3}, [%4];"
                             : "=r"(a[mt][0]), "=r"(a[mt][1]), "=r"(a[mt][2]), "=r"(a[mt][3])
                             : "r"(addr));
            }
            uint32_t b[4][4];
#pragma unroll
            for (int np = 0; np < 4; np++) {
                uint32_t addr = stage + b_off + np * (16 * G1_ROWB) + ks * 32;
                asm volatile("ldmatrix.sync.aligned.m8n8.x4.shared.b16 {%0,%1,%2,%3}, [%4];"
                             : "=r"(b[np][0]), "=r"(b[np][1]), "=r"(b[np][2]), "=r"(b[np][3])
                             : "r"(addr));
            }
#pragma unroll
            for (int mt = 0; mt < 4; mt++) {
#pragma unroll
                for (int nt = 0; nt < 8; nt++) {
                    const uint32_t b0 = b[nt >> 1][(nt & 1) * 2];
                    const uint32_t b1 = b[nt >> 1][(nt & 1) * 2 + 1];
                    asm volatile(
                        "mma.sync.aligned.m16n8k16.row.col.f32.bf16.bf16.f32 "
                        "{%0,%1,%2,%3}, {%4,%5,%6,%7}, {%8,%9}, {%0,%1,%2,%3};"
                        : "+f"(acc[mt][nt][0]), "+f"(acc[mt][nt][1]),
                          "+f"(acc[mt][nt][2]), "+f"(acc[mt][nt][3])
                        : "r"(a[mt][0]), "r"(a[mt][1]), "r"(a[mt][2]), "r"(a[mt][3]),
                          "r"(b0), "r"(b1));
                }
            }
        }
        __syncthreads();
        if (kb + 2 < G1_KITER)
            g1_prefetch(kb + 2, sbase + (kb & 1) * G1_STAGE, bm, bn, t);
        asm volatile("cp.async.commit_group;");
    }

    // epilogue: write fp32 accumulators to g_h1
    const int r_base = bm + mw + (lane >> 2);
    const int c_base = bn + nw + (lane & 3) * 2;
#pragma unroll
    for (int mt = 0; mt < 4; mt++) {
#pragma unroll
        for (int nt = 0; nt < 8; nt++) {
            int r0 = r_base + mt * 16;
            int cc = c_base + nt * 8;
            if (r0 < N_NODES)
                *(float2*)(g_h1 + (size_t)r0 * F1 + cc) = make_float2(acc[mt][nt][0], acc[mt][nt][1]);
            if (r0 + 8 < N_NODES)
                *(float2*)(g_h1 + (size_t)(r0 + 8) * F1 + cc) = make_float2(acc[mt][nt][2], acc[mt][nt][3]);
        }
    }
}

// ---------------- per-node attention scores, layer 1 ------------------------
__global__ void k_scores1(const float* __restrict__ a1) {
    int gw   = (blockIdx.x * blockDim.x + threadIdx.x) >> 5;
    int lane = threadIdx.x & 31;
    if (gw >= N_NODES) return;
    int h  = lane >> 2;
    int cl = (lane & 3) * 16;
    const float4* hp = (const float4*)(g_h1 + (size_t)gw * F1 + lane * 16);
    const float*  as = a1 + h * 128 + cl;
    const float*  ad = a1 + h * 128 + 64 + cl;
    float ss = 0.f, sd = 0.f;
#pragma unroll
    for (int j = 0; j < 4; j++) {
        float4 v = hp[j];
        ss += v.x * as[j * 4 + 0] + v.y * as[j * 4 + 1] + v.z * as[j * 4 + 2] + v.w * as[j * 4 + 3];
        sd += v.x * ad[j * 4 + 0] + v.y * ad[j * 4 + 1] + v.z * ad[j * 4 + 2] + v.w * ad[j * 4 + 3];
    }
    ss += __shfl_xor_sync(0xffffffffu, ss, 1);
    ss += __shfl_xor_sync(0xffffffffu, ss, 2);
    sd += __shfl_xor_sync(0xffffffffu, sd, 1);
    sd += __shfl_xor_sync(0xffffffffu, sd, 2);
    if ((lane & 3) == 0) {
        g_s1s[gw * NHEAD + h] = ss;
        g_s1d[gw * NHEAD + h] = sd;
    }
}

__device__ __forceinline__ float lrelu(float x) { return x > 0.f ? x : NEG * x; }

// ---------------- layer-1 softmax-aggregate ---------------------------------
__global__ __launch_bounds__(256) void k_agg1(const float* __restrict__ b1) {
    int n    = (blockIdx.x * blockDim.x + threadIdx.x) >> 5;
    int lane = threadIdx.x & 31;
    if (n >= N_NODES) return;
    const int beg = g_off[n], end = g_off[n + 1];

    const int h  = lane & 7;
    const int es = lane >> 3;
    const float sdh = g_s1d[n * NHEAD + h];

    float m = -1e30f;
    for (int i = beg + es; i < end; i += 4) {
        int s = g_csr_src[i];
        float e = lrelu(g_s1s[s * NHEAD + h] + sdh);
        m = fmaxf(m, e);
    }
    m = fmaxf(m, __shfl_xor_sync(0xffffffffu, m, 8));
    m = fmaxf(m, __shfl_xor_sync(0xffffffffu, m, 16));

    float den = 0.f;
    for (int i = beg + es; i < end; i += 4) {
        int s = g_csr_src[i];
        float e = lrelu(g_s1s[s * NHEAD + h] + sdh);
        den += __expf(e - m);
    }
    den += __shfl_xor_sync(0xffffffffu, den, 8);
    den += __shfl_xor_sync(0xffffffffu, den, 16);
    den = fmaxf(den, 1e-16f);

    float acc[16];
#pragma unroll
    for (int j = 0; j < 16; j++) acc[j] = 0.f;
    const int hl = lane >> 2;

    for (int i = beg; i < end; i++) {
        int s = g_csr_src[i];
        float alpha = 0.f;
        if (lane < 8) {
            float e = lrelu(g_s1s[s * NHEAD + lane] + sdh);
            alpha = __expf(e - m) / den;
        }
        alpha = __shfl_sync(0xffffffffu, alpha, hl);
        const float4* hp = (const float4*)(g_h1 + (size_t)s * F1 + lane * 16);
#pragma unroll
        for (int j = 0; j < 4; j++) {
            float4 v = hp[j];
            acc[j * 4 + 0] += alpha * v.x;
            acc[j * 4 + 1] += alpha * v.y;
            acc[j * 4 + 2] += alpha * v.z;
            acc[j * 4 + 3] += alpha * v.w;
        }
    }

    const float4* bp = (const float4*)(b1 + lane * 16);
    float4* zp = (float4*)(g_z + (size_t)n * F1 + lane * 16);
#pragma unroll
    for (int j = 0; j < 4; j++) {
        float4 b = bp[j];
        float v0 = acc[j * 4 + 0] + b.x;
        float v1 = acc[j * 4 + 1] + b.y;
        float v2 = acc[j * 4 + 2] + b.z;
        float v3 = acc[j * 4 + 3] + b.w;
        v0 = v0 > 0.f ? v0 : expm1f(v0);
        v1 = v1 > 0.f ? v1 : expm1f(v1);
        v2 = v2 > 0.f ? v2 : expm1f(v2);
        v3 = v3 > 0.f ? v3 : expm1f(v3);
        zp[j] = make_float4(v0, v1, v2, v3);
    }
}

// ---------------- GEMM2: h2 = z[50000,512] @ W2[512,40] ---------------------
__global__ __launch_bounds__(256) void k_gemm2(const float* __restrict__ W2) {
    __shared__ float As[16 * 132];
    __shared__ float Bs[16 * 44];
    const int bm = blockIdx.x * 128;
    const int t  = threadIdx.x;
    const int tx = t & 7;
    const int ty = t >> 3;

    float acc[4][5];
#pragma unroll
    for (int i = 0; i < 4; i++)
#pragma unroll
        for (int j = 0; j < 5; j++) acc[i][j] = 0.f;

    for (int k0 = 0; k0 < F1; k0 += 16) {
#pragma unroll
        for (int it = 0; it < 2; it++) {
            int q  = t + 256 * it;
            int m  = q >> 2;
            int k4 = (q & 3) * 4;
            int row = bm + m;
            float4 v = make_float4(0.f, 0.f, 0.f, 0.f);
            if (row < N_NODES)
                v = *(const float4*)(g_z + (size_t)row * F1 + k0 + k4);
            As[(k4 + 0) * 132 + m] = v.x;
            As[(k4 + 1) * 132 + m] = v.y;
            As[(k4 + 2) * 132 + m] = v.z;
            As[(k4 + 3) * 132 + m] = v.w;
        }
        for (int q = t; q < 16 * NCLASS; q += 256) {
            int kk = q / NCLASS;
            int c  = q - kk * NCLASS;
            Bs[kk * 44 + c] = W2[(size_t)(k0 + kk) * NCLASS + c];
        }
        __syncthreads();
#pragma unroll
        for (int kk = 0; kk < 16; kk++) {
            float4 av = *(const float4*)&As[kk * 132 + ty * 4];
            float a[4] = {av.x, av.y, av.z, av.w};
            float b[5];
#pragma unroll
            for (int j = 0; j < 5; j++) b[j] = Bs[kk * 44 + tx * 5 + j];
#pragma unroll
            for (int i = 0; i < 4; i++)
#pragma unroll
                for (int j = 0; j < 5; j++) acc[i][j] += a[i] * b[j];
        }
        __syncthreads();
    }
#pragma unroll
    for (int i = 0; i < 4; i++) {
        int row = bm + ty * 4 + i;
        if (row < N_NODES) {
#pragma unroll
            for (int j = 0; j < 5; j++)
                g_h2[(size_t)row * NCLASS + tx * 5 + j] = acc[i][j];
        }
    }
}

// ---------------- per-node attention scores, layer 2 ------------------------
__global__ void k_scores2(const float* __restrict__ a2) {
    int gw   = (blockIdx.x * blockDim.x + threadIdx.x) >> 5;
    int lane = threadIdx.x & 31;
    if (gw >= N_NODES) return;
    float v0 = g_h2[(size_t)gw * NCLASS + lane];
    float ss = v0 * a2[lane];
    float sd = v0 * a2[NCLASS + lane];
    if (lane < 8) {
        float v1 = g_h2[(size_t)gw * NCLASS + 32 + lane];
        ss += v1 * a2[32 + lane];
        sd += v1 * a2[NCLASS + 32 + lane];
    }
#pragma unroll
    for (int off = 16; off > 0; off >>= 1) {
        ss += __shfl_xor_sync(0xffffffffu, ss, off);
        sd += __shfl_xor_sync(0xffffffffu, sd, off);
    }
    if (lane == 0) {
        g_s2s[gw] = ss;
        g_s2d[gw] = sd;
    }
}

// ---------------- layer-2 aggregate + bias + log_softmax --------------------
__global__ __launch_bounds__(256) void k_agg2(const float* __restrict__ b2,
                                              float* __restrict__ out) {
    int n    = (blockIdx.x * blockDim.x + threadIdx.x) >> 5;
    int lane = threadIdx.x & 31;
    if (n >= N_NODES) return;
    const int beg = g_off[n], end = g_off[n + 1];
    const float sdn = g_s2d[n];

    float m = -1e30f;
    for (int i = beg + lane; i < end; i += 32) {
        int s = g_csr_src[i];
        m = fmaxf(m, lrelu(g_s2s[s] + sdn));
    }
#pragma unroll
    for (int off = 16; off > 0; off >>= 1)
        m = fmaxf(m, __shfl_xor_sync(0xffffffffu, m, off));

    float den = 0.f;
    for (int i = beg + lane; i < end; i += 32) {
        int s = g_csr_src[i];
        den += __expf(lrelu(g_s2s[s] + sdn) - m);
    }
#pragma unroll
    for (int off = 16; off > 0; off >>= 1)
        den += __shfl_xor_sync(0xffffffffu, den, off);
    den = fmaxf(den, 1e-16f);

    float acc0 = 0.f, acc1 = 0.f;
    for (int i = beg; i < end; i++) {
        int s = g_csr_src[i];
        float e = lrelu(g_s2s[s] + sdn);
        float alpha = __expf(e - m) / den;
        acc0 += alpha * g_h2[(size_t)s * NCLASS + lane];
        if (lane < 8) acc1 += alpha * g_h2[(size_t)s * NCLASS + 32 + lane];
    }

    float v0 = acc0 + b2[lane];
    float v1 = (lane < 8) ? (acc1 + b2[32 + lane]) : -1e30f;

    float mx = fmaxf(v0, v1);
#pragma unroll
    for (int off = 16; off > 0; off >>= 1)
        mx = fmaxf(mx, __shfl_xor_sync(0xffffffffu, mx, off));
    float se = __expf(v0 - mx) + ((lane < 8) ? __expf(v1 - mx) : 0.f);
#pragma unroll
    for (int off = 16; off > 0; off >>= 1)
        se += __shfl_xor_sync(0xffffffffu, se, off);
    float ls = logf(se);

    out[(size_t)n * NCLASS + lane] = v0 - mx - ls;
    if (lane < 8) out[(size_t)n * NCLASS + 32 + lane] = v1 - mx - ls;
}

// ---------------- launch -----------------------------------------------------
extern "C" void kernel_launch(void* const* d_in, const int* in_sizes, int n_in,
                              void* d_out, int out_size) {
    const float* x  = (const float*)d_in[0];
    const int*   el = (const int*)d_in[1];
    const float* W1 = (const float*)d_in[2];
    const float* a1 = (const float*)d_in[3];
    const float* b1 = (const float*)d_in[4];
    const float* W2 = (const float*)d_in[5];
    const float* a2 = (const float*)d_in[6];
    const float* b2 = (const float*)d_in[7];
    float* out = (float*)d_out;

    const int* src = el;
    const int* dst = el + N_EDGES;

    cudaFuncSetAttribute(k_gemm1_mma, cudaFuncAttributeMaxDynamicSharedMemorySize, G1_SMEM);

    const int TB = 256;
    k_zero_deg<<<(N_NODES + TB - 1) / TB, TB>>>();
    k_count<<<(N_EDGES + TB - 1) / TB, TB>>>(dst);
    k_scan<<<1, 1024>>>();
    k_fill<<<(N_EDGES + TB - 1) / TB, TB>>>(src, dst);

    k_split_x<<<(N_NODES * NFEAT / 8 + TB - 1) / TB, TB>>>(x);
    k_split_w<<<(F1 * NFEAT + TB - 1) / TB, TB>>>(W1);

    k_gemm1_mma<<<dim3((N_NODES + G1_BM - 1) / G1_BM, F1 / G1_BN), 256, G1_SMEM>>>();
    k_scores1<<<(N_NODES + 7) / 8, 256>>>(a1);
    k_agg1<<<(N_NODES + 7) / 8, 256>>>(b1);

    k_gemm2<<<(N_NODES + 127) / 128, 256>>>(W2);
    k_scores2<<<(N_NODES + 7) / 8, 256>>>(a2);
    k_agg2<<<(N_NODES + 7) / 8, 256>>>(b2, out);
}

// round 5
// speedup vs baseline: 1.3262x; 1.0614x over previous
#include <cuda_runtime.h>
#include <cuda_bf16.h>
#include <cstdint>

#define N_NODES 50000
#define N_EDGES 800000
#define NFEAT   512
#define NHID    64
#define NHEAD   8
#define F1      512      // NHEAD*NHID
#define NCLASS  40
#define NEG     0.2f

// ---------------- scratch ---------------------------------------------------
__device__ float g_h1[(size_t)N_NODES * F1];
__device__ float g_z [(size_t)N_NODES * F1];
__device__ float g_h2[(size_t)N_NODES * NCLASS];
__device__ float g_s1s[N_NODES * NHEAD];
__device__ float g_s1d[N_NODES * NHEAD];
__device__ float g_s2s[N_NODES];
__device__ float g_s2d[N_NODES];
__device__ int   g_deg[N_NODES];
__device__ int   g_off[N_NODES + 1];
__device__ int   g_cur[N_NODES];
__device__ int   g_csr_src[N_EDGES];
__device__ int   g_bsum[64];
__device__ int   g_bpre[64];
// bf16 split operands for the mma.sync GEMM1
__device__ __nv_bfloat16 g_xhi[(size_t)N_NODES * NFEAT];
__device__ __nv_bfloat16 g_xlo[(size_t)N_NODES * NFEAT];
__device__ __nv_bfloat16 g_WThi[F1 * NFEAT];   // [n][k], n = h*64+c
__device__ __nv_bfloat16 g_WTlo[F1 * NFEAT];

__device__ __forceinline__ uint32_t smem_u32(const void* p) {
    uint32_t a;
    asm("{ .reg .u64 t; cvta.to.shared.u64 t, %1; cvt.u32.u64 %0, t; }" : "=r"(a) : "l"(p));
    return a;
}

// ---------------- CSR construction ------------------------------------------
__global__ void k_zero_deg() {
    int i = blockIdx.x * blockDim.x + threadIdx.x;
    if (i < N_NODES) g_deg[i] = 0;
}
__global__ void k_count(const int* __restrict__ dst) {
    int e = blockIdx.x * blockDim.x + threadIdx.x;
    if (e < N_EDGES) atomicAdd(&g_deg[dst[e]], 1);
}
// block scan: each block (256 thr) scans 1024 elements (4/thread)
__global__ __launch_bounds__(256) void k_scan_blk() {
    __shared__ int wsum[8];
    const int blk = blockIdx.x, t = threadIdx.x;
    const int base = blk * 1024 + t * 4;
    int v[4], s = 0;
#pragma unroll
    for (int j = 0; j < 4; j++) {
        int i = base + j;
        v[j] = (i < N_NODES) ? g_deg[i] : 0;
        s += v[j];
    }
    const int lane = t & 31, w = t >> 5;
    int ps = s;
#pragma unroll
    for (int o = 1; o < 32; o <<= 1) {
        int y = __shfl_up_sync(0xffffffffu, ps, o);
        if (lane >= o) ps += y;
    }
    if (lane == 31) wsum[w] = ps;
    __syncthreads();
    if (w == 0) {
        int ws = (lane < 8) ? wsum[lane] : 0;
#pragma unroll
        for (int o = 1; o < 8; o <<= 1) {
            int y = __shfl_up_sync(0xffffffffu, ws, o);
            if (lane >= o) ws += y;
        }
        if (lane < 8) wsum[lane] = ws;
    }
    __syncthreads();
    int run = ps - s + (w > 0 ? wsum[w - 1] : 0);
#pragma unroll
    for (int j = 0; j < 4; j++) {
        int i = base + j;
        if (i < N_NODES) g_off[i] = run;
        run += v[j];
    }
    if (t == 255) g_bsum[blk] = wsum[7];
}
__global__ void k_scan_top() {       // 1 block, 32 threads, up to 64 block sums
    const int lane = threadIdx.x;
    const int nblk = (N_NODES + 1023) / 1024;
    int a = (lane < nblk) ? g_bsum[lane] : 0;
    int b = (lane + 32 < nblk) ? g_bsum[lane + 32] : 0;
    int pa = a;
#pragma unroll
    for (int o = 1; o < 32; o <<= 1) {
        int y = __shfl_up_sync(0xffffffffu, pa, o);
        if (lane >= o) pa += y;
    }
    int tot0 = __shfl_sync(0xffffffffu, pa, 31);
    int pb = b;
#pragma unroll
    for (int o = 1; o < 32; o <<= 1) {
        int y = __shfl_up_sync(0xffffffffu, pb, o);
        if (lane >= o) pb += y;
    }
    if (lane < nblk) g_bpre[lane] = pa - a;
    if (lane + 32 < nblk) g_bpre[lane + 32] = tot0 + pb - b;
}
__global__ void k_scan_add() {
    int i = blockIdx.x * blockDim.x + threadIdx.x;
    if (i < N_NODES) {
        int o = g_off[i] + g_bpre[i >> 10];
        g_off[i] = o;
        g_cur[i] = o;
    }
    if (i == 0) g_off[N_NODES] = N_EDGES;
}
__global__ void k_fill(const int* __restrict__ src, const int* __restrict__ dst) {
    int e = blockIdx.x * blockDim.x + threadIdx.x;
    if (e < N_EDGES) {
        int d = dst[e];
        int p = atomicAdd(&g_cur[d], 1);
        g_csr_src[p] = src[e];
    }
}

// ---------------- bf16 splits ------------------------------------------------
__global__ void k_split_x(const float* __restrict__ x) {
    int i = blockIdx.x * blockDim.x + threadIdx.x;      // one per 8 elems
    const int total = N_NODES * NFEAT / 8;
    if (i >= total) return;
    const float4* p = (const float4*)x + (size_t)i * 2;
    float4 v0 = p[0], v1 = p[1];
    float f[8] = {v0.x, v0.y, v0.z, v0.w, v1.x, v1.y, v1.z, v1.w};
    __nv_bfloat16 hi[8], lo[8];
#pragma unroll
    for (int j = 0; j < 8; j++) {
        hi[j] = __float2bfloat16(f[j]);
        lo[j] = __float2bfloat16(f[j] - __bfloat162float(hi[j]));
    }
    *(uint4*)(g_xhi + (size_t)i * 8) = *(uint4*)hi;
    *(uint4*)(g_xlo + (size_t)i * 8) = *(uint4*)lo;
}
__global__ void k_split_w(const float* __restrict__ W1) {
    int idx = blockIdx.x * blockDim.x + threadIdx.x;
    if (idx >= F1 * NFEAT) return;
    int n = idx >> 9, k = idx & 511;
    int h = n >> 6, c = n & 63;
    float w = W1[((size_t)h * NFEAT + k) * NHID + c];
    __nv_bfloat16 hi = __float2bfloat16(w);
    __nv_bfloat16 lo = __float2bfloat16(w - __bfloat162float(hi));
    g_WThi[(size_t)n * NFEAT + k] = hi;
    g_WTlo[(size_t)n * NFEAT + k] = lo;
}

// ---------------- GEMM1 (mma.sync bf16): h1 = x @ Wt, 3-term split ----------
// C[50000,512] = A''[50000,1536] * B''[1536,512]
// CTA tile 128x256, BK=32, 8 warps (2m x 4n), warp tile 64x64. 3-stage pipe.
#define G1_BM      128
#define G1_BN      256
#define G1_BK      32
#define G1_KITER   48                // 1536 / 32
#define G1_ROWH    40                // padded row: 32 halves + 8 pad
#define G1_ROWB    80                // bytes
#define G1_ASZ     (G1_BM * G1_ROWB) // 10240
#define G1_BSZ     (G1_BN * G1_ROWB) // 20480
#define G1_STAGE   (G1_ASZ + G1_BSZ) // 30720
#define G1_NSTG    3
#define G1_SMEM    (G1_NSTG * G1_STAGE)

__device__ __forceinline__ void g1_prefetch(int kb, uint32_t stage, int bm, int bn, int t) {
    const int sector = kb >> 4;
    const int k_in   = (kb & 15) * G1_BK;
    const __nv_bfloat16* Asrc = (sector == 1) ? g_xlo  : g_xhi;
    const __nv_bfloat16* Bsrc = (sector == 2) ? g_WTlo : g_WThi;
#pragma unroll
    for (int i = 0; i < 6; i++) {
        int q = t + i * 256;
        if (q < 512) {                       // A: 128 rows x 4 chunks
            int row = q >> 2, c = q & 3;
            int grow = bm + row;
            int ok = grow < N_NODES;
            if (!ok) grow = 0;
            uint32_t dst = stage + row * G1_ROWB + c * 16;
            const void* srcp = Asrc + (size_t)grow * NFEAT + k_in + c * 8;
            int sz = ok ? 16 : 0;
            asm volatile("cp.async.cg.shared.global [%0], [%1], 16, %2;"
                         :: "r"(dst), "l"(srcp), "r"(sz));
        } else {                             // B: 256 rows x 4 chunks
            int qb = q - 512;
            int row = qb >> 2, c = qb & 3;
            uint32_t dst = stage + G1_ASZ + row * G1_ROWB + c * 16;
            const void* srcp = Bsrc + (size_t)(bn + row) * NFEAT + k_in + c * 8;
            asm volatile("cp.async.cg.shared.global [%0], [%1], 16;"
                         :: "r"(dst), "l"(srcp));
        }
    }
}

__global__ __launch_bounds__(256, 1) void k_gemm1_mma() {
    extern __shared__ char dyn[];
    const uint32_t sbase = smem_u32(dyn);
    const int t    = threadIdx.x;
    const int wid  = t >> 5;
    const int lane = t & 31;
    const int bm   = blockIdx.x * G1_BM;
    const int bn   = blockIdx.y * G1_BN;
    const int mw   = (wid >> 2) * 64;
    const int nw   = (wid & 3) * 64;

    float acc[4][8][4];
#pragma unroll
    for (int mt = 0; mt < 4; mt++)
#pragma unroll
        for (int nt = 0; nt < 8; nt++)
#pragma unroll
            for (int j = 0; j < 4; j++) acc[mt][nt][j] = 0.f;

    g1_prefetch(0, sbase, bm, bn, t);
    asm volatile("cp.async.commit_group;");
    g1_prefetch(1, sbase + G1_STAGE, bm, bn, t);
    asm volatile("cp.async.commit_group;");
    g1_prefetch(2, sbase + 2 * G1_STAGE, bm, bn, t);
    asm volatile("cp.async.commit_group;");

    const uint32_t a_off = (mw + (lane & 15)) * G1_ROWB + ((lane >> 4) * 16);
    const uint32_t b_off = G1_ASZ +
        (nw + (lane & 7) + ((lane >> 4) << 3)) * G1_ROWB + (((lane >> 3) & 1) * 16);

    int st = 0;
    for (int kb = 0; kb < G1_KITER; kb++) {
        asm volatile("cp.async.wait_group 2;");
        __syncthreads();
        const uint32_t stage = sbase + st * G1_STAGE;

#pragma unroll
        for (int ks = 0; ks < 2; ks++) {
            uint32_t a[4][4];
#pragma unroll
            for (int mt = 0; mt < 4; mt++) {
                uint32_t addr = stage + a_off + mt * (16 * G1_ROWB) + ks * 32;
                asm volatile("ldmatrix.sync.aligned.m8n8.x4.shared.b16 {%0,%1,%2,%3}, [%4];"
                             : "=r"(a[mt][0]), "=r"(a[mt][1]), "=r"(a[mt][2]), "=r"(a[mt][3])
                             : "r"(addr));
            }
            uint32_t b[4][4];
#pragma unroll
            for (int np = 0; np < 4; np++) {
                uint32_t addr = stage + b_off + np * (16 * G1_ROWB) + ks * 32;
                asm volatile("ldmatrix.sync.aligned.m8n8.x4.shared.b16 {%0,%1,%2,%3}, [%4];"
                             : "=r"(b[np][0]), "=r"(b[np][1]), "=r"(b[np][2]), "=r"(b[np][3])
                             : "r"(addr));
            }
#pragma unroll
            for (int mt = 0; mt < 4; mt++) {
#pragma unroll
                for (int nt = 0; nt < 8; nt++) {
                    const uint32_t b0 = b[nt >> 1][(nt & 1) * 2];
                    const uint32_t b1 = b[nt >> 1][(nt & 1) * 2 + 1];
                    asm volatile(
                        "mma.sync.aligned.m16n8k16.row.col.f32.bf16.bf16.f32 "
                        "{%0,%1,%2,%3}, {%4,%5,%6,%7}, {%8,%9}, {%0,%1,%2,%3};"
                        : "+f"(acc[mt][nt][0]), "+f"(acc[mt][nt][1]),
                          "+f"(acc[mt][nt][2]), "+f"(acc[mt][nt][3])
                        : "r"(a[mt][0]), "r"(a[mt][1]), "r"(a[mt][2]), "r"(a[mt][3]),
                          "r"(b0), "r"(b1));
                }
            }
        }
        __syncthreads();
        if (kb + G1_NSTG < G1_KITER)
            g1_prefetch(kb + G1_NSTG, stage, bm, bn, t);
        asm volatile("cp.async.commit_group;");
        st = (st == G1_NSTG - 1) ? 0 : st + 1;
    }

    // epilogue
    const int r_base = bm + mw + (lane >> 2);
    const int c_base = bn + nw + (lane & 3) * 2;
#pragma unroll
    for (int mt = 0; mt < 4; mt++) {
#pragma unroll
        for (int nt = 0; nt < 8; nt++) {
            int r0 = r_base + mt * 16;
            int cc = c_base + nt * 8;
            if (r0 < N_NODES)
                *(float2*)(g_h1 + (size_t)r0 * F1 + cc) = make_float2(acc[mt][nt][0], acc[mt][nt][1]);
            if (r0 + 8 < N_NODES)
                *(float2*)(g_h1 + (size_t)(r0 + 8) * F1 + cc) = make_float2(acc[mt][nt][2], acc[mt][nt][3]);
        }
    }
}

// ---------------- per-node attention scores, layer 1 ------------------------
__global__ void k_scores1(const float* __restrict__ a1) {
    int gw   = (blockIdx.x * blockDim.x + threadIdx.x) >> 5;
    int lane = threadIdx.x & 31;
    if (gw >= N_NODES) return;
    int h  = lane >> 2;
    int cl = (lane & 3) * 16;
    const float4* hp = (const float4*)(g_h1 + (size_t)gw * F1 + lane * 16);
    const float*  as = a1 + h * 128 + cl;
    const float*  ad = a1 + h * 128 + 64 + cl;
    float ss = 0.f, sd = 0.f;
#pragma unroll
    for (int j = 0; j < 4; j++) {
        float4 v = hp[j];
        ss += v.x * as[j * 4 + 0] + v.y * as[j * 4 + 1] + v.z * as[j * 4 + 2] + v.w * as[j * 4 + 3];
        sd += v.x * ad[j * 4 + 0] + v.y * ad[j * 4 + 1] + v.z * ad[j * 4 + 2] + v.w * ad[j * 4 + 3];
    }
    ss += __shfl_xor_sync(0xffffffffu, ss, 1);
    ss += __shfl_xor_sync(0xffffffffu, ss, 2);
    sd += __shfl_xor_sync(0xffffffffu, sd, 1);
    sd += __shfl_xor_sync(0xffffffffu, sd, 2);
    if ((lane & 3) == 0) {
        g_s1s[gw * NHEAD + h] = ss;
        g_s1d[gw * NHEAD + h] = sd;
    }
}

__device__ __forceinline__ float lrelu(float x) { return x > 0.f ? x : NEG * x; }

// ---------------- layer-1 softmax-aggregate ---------------------------------
__global__ __launch_bounds__(256) void k_agg1(const float* __restrict__ b1) {
    int n    = (blockIdx.x * blockDim.x + threadIdx.x) >> 5;
    int lane = threadIdx.x & 31;
    if (n >= N_NODES) return;
    const int beg = g_off[n], end = g_off[n + 1];

    const int h  = lane & 7;
    const int es = lane >> 3;
    const float sdh = g_s1d[n * NHEAD + h];

    float m = -1e30f;
    for (int i = beg + es; i < end; i += 4) {
        int s = g_csr_src[i];
        float e = lrelu(g_s1s[s * NHEAD + h] + sdh);
        m = fmaxf(m, e);
    }
    m = fmaxf(m, __shfl_xor_sync(0xffffffffu, m, 8));
    m = fmaxf(m, __shfl_xor_sync(0xffffffffu, m, 16));

    float den = 0.f;
    for (int i = beg + es; i < end; i += 4) {
        int s = g_csr_src[i];
        float e = lrelu(g_s1s[s * NHEAD + h] + sdh);
        den += __expf(e - m);
    }
    den += __shfl_xor_sync(0xffffffffu, den, 8);
    den += __shfl_xor_sync(0xffffffffu, den, 16);
    den = fmaxf(den, 1e-16f);

    float acc[16];
#pragma unroll
    for (int j = 0; j < 16; j++) acc[j] = 0.f;
    const int hl = lane >> 2;

    for (int i = beg; i < end; i++) {
        int s = g_csr_src[i];
        float alpha = 0.f;
        if (lane < 8) {
            float e = lrelu(g_s1s[s * NHEAD + lane] + sdh);
            alpha = __expf(e - m) / den;
        }
        alpha = __shfl_sync(0xffffffffu, alpha, hl);
        const float4* hp = (const float4*)(g_h1 + (size_t)s * F1 + lane * 16);
#pragma unroll
        for (int j = 0; j < 4; j++) {
            float4 v = hp[j];
            acc[j * 4 + 0] += alpha * v.x;
            acc[j * 4 + 1] += alpha * v.y;
            acc[j * 4 + 2] += alpha * v.z;
            acc[j * 4 + 3] += alpha * v.w;
        }
    }

    const float4* bp = (const float4*)(b1 + lane * 16);
    float4* zp = (float4*)(g_z + (size_t)n * F1 + lane * 16);
#pragma unroll
    for (int j = 0; j < 4; j++) {
        float4 b = bp[j];
        float v0 = acc[j * 4 + 0] + b.x;
        float v1 = acc[j * 4 + 1] + b.y;
        float v2 = acc[j * 4 + 2] + b.z;
        float v3 = acc[j * 4 + 3] + b.w;
        v0 = v0 > 0.f ? v0 : expm1f(v0);
        v1 = v1 > 0.f ? v1 : expm1f(v1);
        v2 = v2 > 0.f ? v2 : expm1f(v2);
        v3 = v3 > 0.f ? v3 : expm1f(v3);
        zp[j] = make_float4(v0, v1, v2, v3);
    }
}

// ---------------- GEMM2: h2 = z[50000,512] @ W2[512,40] ---------------------
__global__ __launch_bounds__(256) void k_gemm2(const float* __restrict__ W2) {
    __shared__ float As[16 * 132];
    __shared__ float Bs[16 * 44];
    const int bm = blockIdx.x * 128;
    const int t  = threadIdx.x;
    const int tx = t & 7;
    const int ty = t >> 3;

    float acc[4][5];
#pragma unroll
    for (int i = 0; i < 4; i++)
#pragma unroll
        for (int j = 0; j < 5; j++) acc[i][j] = 0.f;

    for (int k0 = 0; k0 < F1; k0 += 16) {
#pragma unroll
        for (int it = 0; it < 2; it++) {
            int q  = t + 256 * it;
            int m  = q >> 2;
            int k4 = (q & 3) * 4;
            int row = bm + m;
            float4 v = make_float4(0.f, 0.f, 0.f, 0.f);
            if (row < N_NODES)
                v = *(const float4*)(g_z + (size_t)row * F1 + k0 + k4);
            As[(k4 + 0) * 132 + m] = v.x;
            As[(k4 + 1) * 132 + m] = v.y;
            As[(k4 + 2) * 132 + m] = v.z;
            As[(k4 + 3) * 132 + m] = v.w;
        }
        for (int q = t; q < 16 * NCLASS; q += 256) {
            int kk = q / NCLASS;
            int c  = q - kk * NCLASS;
            Bs[kk * 44 + c] = W2[(size_t)(k0 + kk) * NCLASS + c];
        }
        __syncthreads();
#pragma unroll
        for (int kk = 0; kk < 16; kk++) {
            float4 av = *(const float4*)&As[kk * 132 + ty * 4];
            float a[4] = {av.x, av.y, av.z, av.w};
            float b[5];
#pragma unroll
            for (int j = 0; j < 5; j++) b[j] = Bs[kk * 44 + tx * 5 + j];
#pragma unroll
            for (int i = 0; i < 4; i++)
#pragma unroll
                for (int j = 0; j < 5; j++) acc[i][j] += a[i] * b[j];
        }
        __syncthreads();
    }
#pragma unroll
    for (int i = 0; i < 4; i++) {
        int row = bm + ty * 4 + i;
        if (row < N_NODES) {
#pragma unroll
            for (int j = 0; j < 5; j++)
                g_h2[(size_t)row * NCLASS + tx * 5 + j] = acc[i][j];
        }
    }
}

// ---------------- per-node attention scores, layer 2 ------------------------
__global__ void k_scores2(const float* __restrict__ a2) {
    int gw   = (blockIdx.x * blockDim.x + threadIdx.x) >> 5;
    int lane = threadIdx.x & 31;
    if (gw >= N_NODES) return;
    float v0 = g_h2[(size_t)gw * NCLASS + lane];
    float ss = v0 * a2[lane];
    float sd = v0 * a2[NCLASS + lane];
    if (lane < 8) {
        float v1 = g_h2[(size_t)gw * NCLASS + 32 + lane];
        ss += v1 * a2[32 + lane];
        sd += v1 * a2[NCLASS + 32 + lane];
    }
#pragma unroll
    for (int off = 16; off > 0; off >>= 1) {
        ss += __shfl_xor_sync(0xffffffffu, ss, off);
        sd += __shfl_xor_sync(0xffffffffu, sd, off);
    }
    if (lane == 0) {
        g_s2s[gw] = ss;
        g_s2d[gw] = sd;
    }
}

// ---------------- layer-2 aggregate + bias + log_softmax --------------------
__global__ __launch_bounds__(256) void k_agg2(const float* __restrict__ b2,
                                              float* __restrict__ out) {
    int n    = (blockIdx.x * blockDim.x + threadIdx.x) >> 5;
    int lane = threadIdx.x & 31;
    if (n >= N_NODES) return;
    const int beg = g_off[n], end = g_off[n + 1];
    const float sdn = g_s2d[n];

    float m = -1e30f;
    for (int i = beg + lane; i < end; i += 32) {
        int s = g_csr_src[i];
        m = fmaxf(m, lrelu(g_s2s[s] + sdn));
    }
#pragma unroll
    for (int off = 16; off > 0; off >>= 1)
        m = fmaxf(m, __shfl_xor_sync(0xffffffffu, m, off));

    float den = 0.f;
    for (int i = beg + lane; i < end; i += 32) {
        int s = g_csr_src[i];
        den += __expf(lrelu(g_s2s[s] + sdn) - m);
    }
#pragma unroll
    for (int off = 16; off > 0; off >>= 1)
        den += __shfl_xor_sync(0xffffffffu, den, off);
    den = fmaxf(den, 1e-16f);

    float acc0 = 0.f, acc1 = 0.f;
    for (int i = beg; i < end; i++) {
        int s = g_csr_src[i];
        float e = lrelu(g_s2s[s] + sdn);
        float alpha = __expf(e - m) / den;
        acc0 += alpha * g_h2[(size_t)s * NCLASS + lane];
        if (lane < 8) acc1 += alpha * g_h2[(size_t)s * NCLASS + 32 + lane];
    }

    float v0 = acc0 + b2[lane];
    float v1 = (lane < 8) ? (acc1 + b2[32 + lane]) : -1e30f;

    float mx = fmaxf(v0, v1);
#pragma unroll
    for (int off = 16; off > 0; off >>= 1)
        mx = fmaxf(mx, __shfl_xor_sync(0xffffffffu, mx, off));
    float se = __expf(v0 - mx) + ((lane < 8) ? __expf(v1 - mx) : 0.f);
#pragma unroll
    for (int off = 16; off > 0; off >>= 1)
        se += __shfl_xor_sync(0xffffffffu, se, off);
    float ls = logf(se);

    out[(size_t)n * NCLASS + lane] = v0 - mx - ls;
    if (lane < 8) out[(size_t)n * NCLASS + 32 + lane] = v1 - mx - ls;
}

// ---------------- launch -----------------------------------------------------
extern "C" void kernel_launch(void* const* d_in, const int* in_sizes, int n_in,
                              void* d_out, int out_size) {
    const float* x  = (const float*)d_in[0];
    const int*   el = (const int*)d_in[1];
    const float* W1 = (const float*)d_in[2];
    const float* a1 = (const float*)d_in[3];
    const float* b1 = (const float*)d_in[4];
    const float* W2 = (const float*)d_in[5];
    const float* a2 = (const float*)d_in[6];
    const float* b2 = (const float*)d_in[7];
    float* out = (float*)d_out;

    const int* src = el;
    const int* dst = el + N_EDGES;

    cudaFuncSetAttribute(k_gemm1_mma, cudaFuncAttributeMaxDynamicSharedMemorySize, G1_SMEM);

    const int TB = 256;
    const int NBLK = (N_NODES + 1023) / 1024;

    // order chosen so launch index 3 (the ncu-profiled slot) is the GEMM
    k_split_x<<<(N_NODES * NFEAT / 8 + TB - 1) / TB, TB>>>(x);          // 0
    k_split_w<<<(F1 * NFEAT + TB - 1) / TB, TB>>>(W1);                  // 1
    k_zero_deg<<<(N_NODES + TB - 1) / TB, TB>>>();                      // 2
    k_gemm1_mma<<<dim3((N_NODES + G1_BM - 1) / G1_BM, F1 / G1_BN), 256, G1_SMEM>>>(); // 3
    k_count<<<(N_EDGES + TB - 1) / TB, TB>>>(dst);                      // 4
    k_scan_blk<<<NBLK, 256>>>();                                        // 5
    k_scan_top<<<1, 32>>>();                                            // 6
    k_scan_add<<<(N_NODES + TB - 1) / TB, TB>>>();                      // 7
    k_fill<<<(N_EDGES + TB - 1) / TB, TB>>>(src, dst);                  // 8
    k_scores1<<<(N_NODES + 7) / 8, 256>>>(a1);                          // 9
    k_agg1<<<(N_NODES + 7) / 8, 256>>>(b1);                             // 10
    k_gemm2<<<(N_NODES + 127) / 128, 256>>>(W2);                        // 11
    k_scores2<<<(N_NODES + 7) / 8, 256>>>(a2);                          // 12
    k_agg2<<<(N_NODES + 7) / 8, 256>>>(b2, out);                        // 13
}

// round 6
// speedup vs baseline: 1.4035x; 1.0583x over previous
#include <cuda_runtime.h>
#include <cuda_bf16.h>
#include <cstdint>

#define N_NODES 50000
#define N_EDGES 800000
#define NFEAT   512
#define NHID    64
#define NHEAD   8
#define F1      512      // NHEAD*NHID
#define NCLASS  40
#define NEG     0.2f

// ---------------- scratch ---------------------------------------------------
__device__ float g_h1[(size_t)N_NODES * F1];
__device__ float g_z [(size_t)N_NODES * F1];
__device__ float g_h2[(size_t)N_NODES * NCLASS];
__device__ float g_s1s[N_NODES * NHEAD];
__device__ float g_s1d[N_NODES * NHEAD];
__device__ float g_s2s[N_NODES];
__device__ float g_s2d[N_NODES];
__device__ int   g_deg[N_NODES];
__device__ int   g_off[N_NODES + 1];
__device__ int   g_cur[N_NODES];
__device__ int   g_csr_src[N_EDGES];
__device__ int   g_bsum[64];
__device__ int   g_bpre[64];
// bf16 split operands for the mma.sync GEMM1
__device__ __nv_bfloat16 g_xhi[(size_t)N_NODES * NFEAT];
__device__ __nv_bfloat16 g_xlo[(size_t)N_NODES * NFEAT];
__device__ __nv_bfloat16 g_WThi[F1 * NFEAT];   // [n][k], n = h*64+c
__device__ __nv_bfloat16 g_WTlo[F1 * NFEAT];

__device__ __forceinline__ uint32_t smem_u32(const void* p) {
    uint32_t a;
    asm("{ .reg .u64 t; cvta.to.shared.u64 t, %1; cvt.u32.u64 %0, t; }" : "=r"(a) : "l"(p));
    return a;
}

// ---------------- CSR construction ------------------------------------------
__global__ void k_zero_deg() {
    int i = blockIdx.x * blockDim.x + threadIdx.x;
    if (i < N_NODES) g_deg[i] = 0;
}
__global__ void k_count(const int* __restrict__ dst) {
    int e = blockIdx.x * blockDim.x + threadIdx.x;
    if (e < N_EDGES) atomicAdd(&g_deg[dst[e]], 1);
}
// block scan: each block (256 thr) scans 1024 elements (4/thread)
__global__ __launch_bounds__(256) void k_scan_blk() {
    __shared__ int wsum[8];
    const int blk = blockIdx.x, t = threadIdx.x;
    const int base = blk * 1024 + t * 4;
    int v[4], s = 0;
#pragma unroll
    for (int j = 0; j < 4; j++) {
        int i = base + j;
        v[j] = (i < N_NODES) ? g_deg[i] : 0;
        s += v[j];
    }
    const int lane = t & 31, w = t >> 5;
    int ps = s;
#pragma unroll
    for (int o = 1; o < 32; o <<= 1) {
        int y = __shfl_up_sync(0xffffffffu, ps, o);
        if (lane >= o) ps += y;
    }
    if (lane == 31) wsum[w] = ps;
    __syncthreads();
    if (w == 0) {
        int ws = (lane < 8) ? wsum[lane] : 0;
#pragma unroll
        for (int o = 1; o < 8; o <<= 1) {
            int y = __shfl_up_sync(0xffffffffu, ws, o);
            if (lane >= o) ws += y;
        }
        if (lane < 8) wsum[lane] = ws;
    }
    __syncthreads();
    int run = ps - s + (w > 0 ? wsum[w - 1] : 0);
#pragma unroll
    for (int j = 0; j < 4; j++) {
        int i = base + j;
        if (i < N_NODES) g_off[i] = run;
        run += v[j];
    }
    if (t == 255) g_bsum[blk] = wsum[7];
}
__global__ void k_scan_top() {       // 1 block, 32 threads, up to 64 block sums
    const int lane = threadIdx.x;
    const int nblk = (N_NODES + 1023) / 1024;
    int a = (lane < nblk) ? g_bsum[lane] : 0;
    int b = (lane + 32 < nblk) ? g_bsum[lane + 32] : 0;
    int pa = a;
#pragma unroll
    for (int o = 1; o < 32; o <<= 1) {
        int y = __shfl_up_sync(0xffffffffu, pa, o);
        if (lane >= o) pa += y;
    }
    int tot0 = __shfl_sync(0xffffffffu, pa, 31);
    int pb = b;
#pragma unroll
    for (int o = 1; o < 32; o <<= 1) {
        int y = __shfl_up_sync(0xffffffffu, pb, o);
        if (lane >= o) pb += y;
    }
    if (lane < nblk) g_bpre[lane] = pa - a;
    if (lane + 32 < nblk) g_bpre[lane + 32] = tot0 + pb - b;
}
__global__ void k_scan_add() {
    int i = blockIdx.x * blockDim.x + threadIdx.x;
    if (i < N_NODES) {
        int o = g_off[i] + g_bpre[i >> 10];
        g_off[i] = o;
        g_cur[i] = o;
    }
    if (i == 0) g_off[N_NODES] = N_EDGES;
}
__global__ void k_fill(const int* __restrict__ src, const int* __restrict__ dst) {
    int e = blockIdx.x * blockDim.x + threadIdx.x;
    if (e < N_EDGES) {
        int d = dst[e];
        int p = atomicAdd(&g_cur[d], 1);
        g_csr_src[p] = src[e];
    }
}

// ---------------- bf16 splits ------------------------------------------------
__global__ void k_split_x(const float* __restrict__ x) {
    int i = blockIdx.x * blockDim.x + threadIdx.x;      // one per 8 elems
    const int total = N_NODES * NFEAT / 8;
    if (i >= total) return;
    const float4* p = (const float4*)x + (size_t)i * 2;
    float4 v0 = p[0], v1 = p[1];
    float f[8] = {v0.x, v0.y, v0.z, v0.w, v1.x, v1.y, v1.z, v1.w};
    __nv_bfloat16 hi[8], lo[8];
#pragma unroll
    for (int j = 0; j < 8; j++) {
        hi[j] = __float2bfloat16(f[j]);
        lo[j] = __float2bfloat16(f[j] - __bfloat162float(hi[j]));
    }
    *(uint4*)(g_xhi + (size_t)i * 8) = *(uint4*)hi;
    *(uint4*)(g_xlo + (size_t)i * 8) = *(uint4*)lo;
}
__global__ void k_split_w(const float* __restrict__ W1) {
    int idx = blockIdx.x * blockDim.x + threadIdx.x;
    if (idx >= F1 * NFEAT) return;
    int n = idx >> 9, k = idx & 511;
    int h = n >> 6, c = n & 63;
    float w = W1[((size_t)h * NFEAT + k) * NHID + c];
    __nv_bfloat16 hi = __float2bfloat16(w);
    __nv_bfloat16 lo = __float2bfloat16(w - __bfloat162float(hi));
    g_WThi[(size_t)n * NFEAT + k] = hi;
    g_WTlo[(size_t)n * NFEAT + k] = lo;
}

// ---------------- GEMM1 (mma.sync bf16): h1 = x @ Wt, 3-term split ----------
// C[50000,512] = A''[50000,1536] * B''[1536,512]
// CTA tile 128x128, BK=32, 8 warps (2m x 4n), warp tile 64x32. 3-stage pipe.
// 2 CTAs/SM (launch_bounds minctasm=2) for latency hiding.
#define G1_BM      128
#define G1_BN      128
#define G1_BK      32
#define G1_KITER   48                // 1536 / 32
#define G1_ROWB    80                // padded row bytes: 32 halves + 8 pad
#define G1_ASZ     (G1_BM * G1_ROWB) // 10240
#define G1_BSZ     (G1_BN * G1_ROWB) // 10240
#define G1_STAGE   (G1_ASZ + G1_BSZ) // 20480
#define G1_NSTG    3
#define G1_SMEM    (G1_NSTG * G1_STAGE)   // 61440

__device__ __forceinline__ void g1_prefetch(int kb, uint32_t stage, int bm, int bn, int t) {
    const int sector = kb >> 4;
    const int k_in   = (kb & 15) * G1_BK;
    const __nv_bfloat16* Asrc = (sector == 1) ? g_xlo  : g_xhi;
    const __nv_bfloat16* Bsrc = (sector == 2) ? g_WTlo : g_WThi;
#pragma unroll
    for (int i = 0; i < 4; i++) {
        int q = t + i * 256;
        if (q < 512) {                       // A: 128 rows x 4 chunks
            int row = q >> 2, c = q & 3;
            int grow = bm + row;
            int ok = grow < N_NODES;
            if (!ok) grow = 0;
            uint32_t dst = stage + row * G1_ROWB + c * 16;
            const void* srcp = Asrc + (size_t)grow * NFEAT + k_in + c * 8;
            int sz = ok ? 16 : 0;
            asm volatile("cp.async.cg.shared.global [%0], [%1], 16, %2;"
                         :: "r"(dst), "l"(srcp), "r"(sz));
        } else {                             // B: 128 rows x 4 chunks
            int qb = q - 512;
            int row = qb >> 2, c = qb & 3;
            uint32_t dst = stage + G1_ASZ + row * G1_ROWB + c * 16;
            const void* srcp = Bsrc + (size_t)(bn + row) * NFEAT + k_in + c * 8;
            asm volatile("cp.async.cg.shared.global [%0], [%1], 16;"
                         :: "r"(dst), "l"(srcp));
        }
    }
}

__global__ __launch_bounds__(256, 2) void k_gemm1_mma() {
    extern __shared__ char dyn[];
    const uint32_t sbase = smem_u32(dyn);
    const int t    = threadIdx.x;
    const int wid  = t >> 5;
    const int lane = t & 31;
    const int bm   = blockIdx.x * G1_BM;
    const int bn   = blockIdx.y * G1_BN;
    const int mw   = (wid >> 2) * 64;        // warp m offset (2 rows of warps)
    const int nw   = (wid & 3) * 32;         // warp n offset (4 cols of warps)

    float acc[4][4][4];
#pragma unroll
    for (int mt = 0; mt < 4; mt++)
#pragma unroll
        for (int nt = 0; nt < 4; nt++)
#pragma unroll
            for (int j = 0; j < 4; j++) acc[mt][nt][j] = 0.f;

    g1_prefetch(0, sbase, bm, bn, t);
    asm volatile("cp.async.commit_group;");
    g1_prefetch(1, sbase + G1_STAGE, bm, bn, t);
    asm volatile("cp.async.commit_group;");
    g1_prefetch(2, sbase + 2 * G1_STAGE, bm, bn, t);
    asm volatile("cp.async.commit_group;");

    const uint32_t a_off = (mw + (lane & 15)) * G1_ROWB + ((lane >> 4) * 16);
    const uint32_t b_off = G1_ASZ +
        (nw + (lane & 7) + ((lane >> 4) << 3)) * G1_ROWB + (((lane >> 3) & 1) * 16);

    int st = 0;
    for (int kb = 0; kb < G1_KITER; kb++) {
        asm volatile("cp.async.wait_group 2;");
        __syncthreads();
        const uint32_t stage = sbase + st * G1_STAGE;

#pragma unroll
        for (int ks = 0; ks < 2; ks++) {
            uint32_t a[4][4];
#pragma unroll
            for (int mt = 0; mt < 4; mt++) {
                uint32_t addr = stage + a_off + mt * (16 * G1_ROWB) + ks * 32;
                asm volatile("ldmatrix.sync.aligned.m8n8.x4.shared.b16 {%0,%1,%2,%3}, [%4];"
                             : "=r"(a[mt][0]), "=r"(a[mt][1]), "=r"(a[mt][2]), "=r"(a[mt][3])
                             : "r"(addr));
            }
            uint32_t b[2][4];
#pragma unroll
            for (int np = 0; np < 2; np++) {
                uint32_t addr = stage + b_off + np * (16 * G1_ROWB) + ks * 32;
                asm volatile("ldmatrix.sync.aligned.m8n8.x4.shared.b16 {%0,%1,%2,%3}, [%4];"
                             : "=r"(b[np][0]), "=r"(b[np][1]), "=r"(b[np][2]), "=r"(b[np][3])
                             : "r"(addr));
            }
#pragma unroll
            for (int mt = 0; mt < 4; mt++) {
#pragma unroll
                for (int nt = 0; nt < 4; nt++) {
                    const uint32_t b0 = b[nt >> 1][(nt & 1) * 2];
                    const uint32_t b1 = b[nt >> 1][(nt & 1) * 2 + 1];
                    asm volatile(
                        "mma.sync.aligned.m16n8k16.row.col.f32.bf16.bf16.f32 "
                        "{%0,%1,%2,%3}, {%4,%5,%6,%7}, {%8,%9}, {%0,%1,%2,%3};"
                        : "+f"(acc[mt][nt][0]), "+f"(acc[mt][nt][1]),
                          "+f"(acc[mt][nt][2]), "+f"(acc[mt][nt][3])
                        : "r"(a[mt][0]), "r"(a[mt][1]), "r"(a[mt][2]), "r"(a[mt][3]),
                          "r"(b0), "r"(b1));
                }
            }
        }
        __syncthreads();
        if (kb + G1_NSTG < G1_KITER)
            g1_prefetch(kb + G1_NSTG, stage, bm, bn, t);
        asm volatile("cp.async.commit_group;");
        st = (st == G1_NSTG - 1) ? 0 : st + 1;
    }

    // epilogue
    const int r_base = bm + mw + (lane >> 2);
    const int c_base = bn + nw + (lane & 3) * 2;
#pragma unroll
    for (int mt = 0; mt < 4; mt++) {
#pragma unroll
        for (int nt = 0; nt < 4; nt++) {
            int r0 = r_base + mt * 16;
            int cc = c_base + nt * 8;
            if (r0 < N_NODES)
                *(float2*)(g_h1 + (size_t)r0 * F1 + cc) = make_float2(acc[mt][nt][0], acc[mt][nt][1]);
            if (r0 + 8 < N_NODES)
                *(float2*)(g_h1 + (size_t)(r0 + 8) * F1 + cc) = make_float2(acc[mt][nt][2], acc[mt][nt][3]);
        }
    }
}

// ---------------- per-node attention scores, layer 1 ------------------------
__global__ void k_scores1(const float* __restrict__ a1) {
    int gw   = (blockIdx.x * blockDim.x + threadIdx.x) >> 5;
    int lane = threadIdx.x & 31;
    if (gw >= N_NODES) return;
    int h  = lane >> 2;
    int cl = (lane & 3) * 16;
    const float4* hp = (const float4*)(g_h1 + (size_t)gw * F1 + lane * 16);
    const float*  as = a1 + h * 128 + cl;
    const float*  ad = a1 + h * 128 + 64 + cl;
    float ss = 0.f, sd = 0.f;
#pragma unroll
    for (int j = 0; j < 4; j++) {
        float4 v = hp[j];
        ss += v.x * as[j * 4 + 0] + v.y * as[j * 4 + 1] + v.z * as[j * 4 + 2] + v.w * as[j * 4 + 3];
        sd += v.x * ad[j * 4 + 0] + v.y * ad[j * 4 + 1] + v.z * ad[j * 4 + 2] + v.w * ad[j * 4 + 3];
    }
    ss += __shfl_xor_sync(0xffffffffu, ss, 1);
    ss += __shfl_xor_sync(0xffffffffu, ss, 2);
    sd += __shfl_xor_sync(0xffffffffu, sd, 1);
    sd += __shfl_xor_sync(0xffffffffu, sd, 2);
    if ((lane & 3) == 0) {
        g_s1s[gw * NHEAD + h] = ss;
        g_s1d[gw * NHEAD + h] = sd;
    }
}

__device__ __forceinline__ float lrelu(float x) { return x > 0.f ? x : NEG * x; }

// ---------------- layer-1 softmax-aggregate ---------------------------------
__global__ __launch_bounds__(256) void k_agg1(const float* __restrict__ b1) {
    int n    = (blockIdx.x * blockDim.x + threadIdx.x) >> 5;
    int lane = threadIdx.x & 31;
    if (n >= N_NODES) return;
    const int beg = g_off[n], end = g_off[n + 1];

    const int h  = lane & 7;
    const int es = lane >> 3;
    const float sdh = g_s1d[n * NHEAD + h];

    float m = -1e30f;
    for (int i = beg + es; i < end; i += 4) {
        int s = g_csr_src[i];
        float e = lrelu(g_s1s[s * NHEAD + h] + sdh);
        m = fmaxf(m, e);
    }
    m = fmaxf(m, __shfl_xor_sync(0xffffffffu, m, 8));
    m = fmaxf(m, __shfl_xor_sync(0xffffffffu, m, 16));

    float den = 0.f;
    for (int i = beg + es; i < end; i += 4) {
        int s = g_csr_src[i];
        float e = lrelu(g_s1s[s * NHEAD + h] + sdh);
        den += __expf(e - m);
    }
    den += __shfl_xor_sync(0xffffffffu, den, 8);
    den += __shfl_xor_sync(0xffffffffu, den, 16);
    den = fmaxf(den, 1e-16f);

    float acc[16];
#pragma unroll
    for (int j = 0; j < 16; j++) acc[j] = 0.f;
    const int hl = lane >> 2;

    for (int i = beg; i < end; i++) {
        int s = g_csr_src[i];
        float alpha = 0.f;
        if (lane < 8) {
            float e = lrelu(g_s1s[s * NHEAD + lane] + sdh);
            alpha = __expf(e - m) / den;
        }
        alpha = __shfl_sync(0xffffffffu, alpha, hl);
        const float4* hp = (const float4*)(g_h1 + (size_t)s * F1 + lane * 16);
#pragma unroll
        for (int j = 0; j < 4; j++) {
            float4 v = hp[j];
            acc[j * 4 + 0] += alpha * v.x;
            acc[j * 4 + 1] += alpha * v.y;
            acc[j * 4 + 2] += alpha * v.z;
            acc[j * 4 + 3] += alpha * v.w;
        }
    }

    const float4* bp = (const float4*)(b1 + lane * 16);
    float4* zp = (float4*)(g_z + (size_t)n * F1 + lane * 16);
#pragma unroll
    for (int j = 0; j < 4; j++) {
        float4 b = bp[j];
        float v0 = acc[j * 4 + 0] + b.x;
        float v1 = acc[j * 4 + 1] + b.y;
        float v2 = acc[j * 4 + 2] + b.z;
        float v3 = acc[j * 4 + 3] + b.w;
        v0 = v0 > 0.f ? v0 : expm1f(v0);
        v1 = v1 > 0.f ? v1 : expm1f(v1);
        v2 = v2 > 0.f ? v2 : expm1f(v2);
        v3 = v3 > 0.f ? v3 : expm1f(v3);
        zp[j] = make_float4(v0, v1, v2, v3);
    }
}

// ---------------- GEMM2: h2 = z[50000,512] @ W2[512,40] ---------------------
__global__ __launch_bounds__(256) void k_gemm2(const float* __restrict__ W2) {
    __shared__ float As[16 * 132];
    __shared__ float Bs[16 * 44];
    const int bm = blockIdx.x * 128;
    const int t  = threadIdx.x;
    const int tx = t & 7;
    const int ty = t >> 3;

    float acc[4][5];
#pragma unroll
    for (int i = 0; i < 4; i++)
#pragma unroll
        for (int j = 0; j < 5; j++) acc[i][j] = 0.f;

    for (int k0 = 0; k0 < F1; k0 += 16) {
#pragma unroll
        for (int it = 0; it < 2; it++) {
            int q  = t + 256 * it;
            int m  = q >> 2;
            int k4 = (q & 3) * 4;
            int row = bm + m;
            float4 v = make_float4(0.f, 0.f, 0.f, 0.f);
            if (row < N_NODES)
                v = *(const float4*)(g_z + (size_t)row * F1 + k0 + k4);
            As[(k4 + 0) * 132 + m] = v.x;
            As[(k4 + 1) * 132 + m] = v.y;
            As[(k4 + 2) * 132 + m] = v.z;
            As[(k4 + 3) * 132 + m] = v.w;
        }
        for (int q = t; q < 16 * NCLASS; q += 256) {
            int kk = q / NCLASS;
            int c  = q - kk * NCLASS;
            Bs[kk * 44 + c] = W2[(size_t)(k0 + kk) * NCLASS + c];
        }
        __syncthreads();
#pragma unroll
        for (int kk = 0; kk < 16; kk++) {
            float4 av = *(const float4*)&As[kk * 132 + ty * 4];
            float a[4] = {av.x, av.y, av.z, av.w};
            float b[5];
#pragma unroll
            for (int j = 0; j < 5; j++) b[j] = Bs[kk * 44 + tx * 5 + j];
#pragma unroll
            for (int i = 0; i < 4; i++)
#pragma unroll
                for (int j = 0; j < 5; j++) acc[i][j] += a[i] * b[j];
        }
        __syncthreads();
    }
#pragma unroll
    for (int i = 0; i < 4; i++) {
        int row = bm + ty * 4 + i;
        if (row < N_NODES) {
#pragma unroll
            for (int j = 0; j < 5; j++)
                g_h2[(size_t)row * NCLASS + tx * 5 + j] = acc[i][j];
        }
    }
}

// ---------------- per-node attention scores, layer 2 ------------------------
__global__ void k_scores2(const float* __restrict__ a2) {
    int gw   = (blockIdx.x * blockDim.x + threadIdx.x) >> 5;
    int lane = threadIdx.x & 31;
    if (gw >= N_NODES) return;
    float v0 = g_h2[(size_t)gw * NCLASS + lane];
    float ss = v0 * a2[lane];
    float sd = v0 * a2[NCLASS + lane];
    if (lane < 8) {
        float v1 = g_h2[(size_t)gw * NCLASS + 32 + lane];
        ss += v1 * a2[32 + lane];
        sd += v1 * a2[NCLASS + 32 + lane];
    }
#pragma unroll
    for (int off = 16; off > 0; off >>= 1) {
        ss += __shfl_xor_sync(0xffffffffu, ss, off);
        sd += __shfl_xor_sync(0xffffffffu, sd, off);
    }
    if (lane == 0) {
        g_s2s[gw] = ss;
        g_s2d[gw] = sd;
    }
}

// ---------------- layer-2 aggregate + bias + log_softmax --------------------
__global__ __launch_bounds__(256) void k_agg2(const float* __restrict__ b2,
                                              float* __restrict__ out) {
    int n    = (blockIdx.x * blockDim.x + threadIdx.x) >> 5;
    int lane = threadIdx.x & 31;
    if (n >= N_NODES) return;
    const int beg = g_off[n], end = g_off[n + 1];
    const float sdn = g_s2d[n];

    float m = -1e30f;
    for (int i = beg + lane; i < end; i += 32) {
        int s = g_csr_src[i];
        m = fmaxf(m, lrelu(g_s2s[s] + sdn));
    }
#pragma unroll
    for (int off = 16; off > 0; off >>= 1)
        m = fmaxf(m, __shfl_xor_sync(0xffffffffu, m, off));

    float den = 0.f;
    for (int i = beg + lane; i < end; i += 32) {
        int s = g_csr_src[i];
        den += __expf(lrelu(g_s2s[s] + sdn) - m);
    }
#pragma unroll
    for (int off = 16; off > 0; off >>= 1)
        den += __shfl_xor_sync(0xffffffffu, den, off);
    den = fmaxf(den, 1e-16f);

    float acc0 = 0.f, acc1 = 0.f;
    for (int i = beg; i < end; i++) {
        int s = g_csr_src[i];
        float e = lrelu(g_s2s[s] + sdn);
        float alpha = __expf(e - m) / den;
        acc0 += alpha * g_h2[(size_t)s * NCLASS + lane];
        if (lane < 8) acc1 += alpha * g_h2[(size_t)s * NCLASS + 32 + lane];
    }

    float v0 = acc0 + b2[lane];
    float v1 = (lane < 8) ? (acc1 + b2[32 + lane]) : -1e30f;

    float mx = fmaxf(v0, v1);
#pragma unroll
    for (int off = 16; off > 0; off >>= 1)
        mx = fmaxf(mx, __shfl_xor_sync(0xffffffffu, mx, off));
    float se = __expf(v0 - mx) + ((lane < 8) ? __expf(v1 - mx) : 0.f);
#pragma unroll
    for (int off = 16; off > 0; off >>= 1)
        se += __shfl_xor_sync(0xffffffffu, se, off);
    float ls = logf(se);

    out[(size_t)n * NCLASS + lane] = v0 - mx - ls;
    if (lane < 8) out[(size_t)n * NCLASS + 32 + lane] = v1 - mx - ls;
}

// ---------------- launch -----------------------------------------------------
extern "C" void kernel_launch(void* const* d_in, const int* in_sizes, int n_in,
                              void* d_out, int out_size) {
    const float* x  = (const float*)d_in[0];
    const int*   el = (const int*)d_in[1];
    const float* W1 = (const float*)d_in[2];
    const float* a1 = (const float*)d_in[3];
    const float* b1 = (const float*)d_in[4];
    const float* W2 = (const float*)d_in[5];
    const float* a2 = (const float*)d_in[6];
    const float* b2 = (const float*)d_in[7];
    float* out = (float*)d_out;

    const int* src = el;
    const int* dst = el + N_EDGES;

    cudaFuncSetAttribute(k_gemm1_mma, cudaFuncAttributeMaxDynamicSharedMemorySize, G1_SMEM);

    const int TB = 256;
    const int NBLK = (N_NODES + 1023) / 1024;

    // launch index 3 (the ncu-profiled slot) is the GEMM
    k_split_x<<<(N_NODES * NFEAT / 8 + TB - 1) / TB, TB>>>(x);          // 0
    k_split_w<<<(F1 * NFEAT + TB - 1) / TB, TB>>>(W1);                  // 1
    k_zero_deg<<<(N_NODES + TB - 1) / TB, TB>>>();                      // 2
    k_gemm1_mma<<<dim3((N_NODES + G1_BM - 1) / G1_BM, F1 / G1_BN), 256, G1_SMEM>>>(); // 3
    k_count<<<(N_EDGES + TB - 1) / TB, TB>>>(dst);                      // 4
    k_scan_blk<<<NBLK, 256>>>();                                        // 5
    k_scan_top<<<1, 32>>>();                                            // 6
    k_scan_add<<<(N_NODES + TB - 1) / TB, TB>>>();                      // 7
    k_fill<<<(N_EDGES + TB - 1) / TB, TB>>>(src, dst);                  // 8
    k_scores1<<<(N_NODES + 7) / 8, 256>>>(a1);                          // 9
    k_agg1<<<(N_NODES + 7) / 8, 256>>>(b1);                             // 10
    k_gemm2<<<(N_NODES + 127) / 128, 256>>>(W2);                        // 11
    k_scores2<<<(N_NODES + 7) / 8, 256>>>(a2);                          // 12
    k_agg2<<<(N_NODES + 7) / 8, 256>>>(b2, out);                        // 13
}

// round 7
// speedup vs baseline: 1.6365x; 1.1660x over previous
#include <cuda_runtime.h>
#include <cuda_bf16.h>
#include <cstdint>

#define N_NODES 50000
#define N_EDGES 800000
#define NFEAT   512
#define NHID    64
#define NHEAD   8
#define F1      512      // NHEAD*NHID
#define NCLASS  40
#define N2PAD   64
#define NEG     0.2f

// ---------------- scratch ---------------------------------------------------
__device__ float g_h1[(size_t)N_NODES * F1];
__device__ float g_h2[(size_t)N_NODES * NCLASS];
__device__ float g_s1s[N_NODES * NHEAD];
__device__ float g_s1d[N_NODES * NHEAD];
__device__ float g_s2s[N_NODES];
__device__ float g_s2d[N_NODES];
__device__ int   g_deg[N_NODES];
__device__ int   g_off[N_NODES + 1];
__device__ int   g_cur[N_NODES];
__device__ int   g_csr_src[N_EDGES];
__device__ int   g_bsum[64];
__device__ int   g_bpre[64];
// bf16 split operands
__device__ __nv_bfloat16 g_xhi[(size_t)N_NODES * NFEAT];
__device__ __nv_bfloat16 g_xlo[(size_t)N_NODES * NFEAT];
__device__ __nv_bfloat16 g_WThi[F1 * NFEAT];   // [n][k], n = h*64+c
__device__ __nv_bfloat16 g_WTlo[F1 * NFEAT];
__device__ __nv_bfloat16 g_zhi[(size_t)N_NODES * F1];   // layer-2 input, split
__device__ __nv_bfloat16 g_zlo[(size_t)N_NODES * F1];
__device__ __nv_bfloat16 g_W2hi[N2PAD * F1];   // [n][k], n padded to 64
__device__ __nv_bfloat16 g_W2lo[N2PAD * F1];

__device__ __forceinline__ uint32_t smem_u32(const void* p) {
    uint32_t a;
    asm("{ .reg .u64 t; cvta.to.shared.u64 t, %1; cvt.u32.u64 %0, t; }" : "=r"(a) : "l"(p));
    return a;
}

#define LDSM_X4(r0, r1, r2, r3, addr) \
    asm volatile("ldmatrix.sync.aligned.m8n8.x4.shared.b16 {%0,%1,%2,%3}, [%4];" \
                 : "=r"(r0), "=r"(r1), "=r"(r2), "=r"(r3) : "r"(addr))
#define MMA16816(acc, a, b0, b1) \
    asm volatile("mma.sync.aligned.m16n8k16.row.col.f32.bf16.bf16.f32 " \
                 "{%0,%1,%2,%3}, {%4,%5,%6,%7}, {%8,%9}, {%0,%1,%2,%3};" \
                 : "+f"((acc)[0]), "+f"((acc)[1]), "+f"((acc)[2]), "+f"((acc)[3]) \
                 : "r"((a)[0]), "r"((a)[1]), "r"((a)[2]), "r"((a)[3]), "r"(b0), "r"(b1))

// ---------------- CSR construction ------------------------------------------
__global__ void k_zero_deg() {
    int i = blockIdx.x * blockDim.x + threadIdx.x;
    if (i < N_NODES) g_deg[i] = 0;
}
__global__ void k_count(const int* __restrict__ dst) {
    int e = blockIdx.x * blockDim.x + threadIdx.x;
    if (e < N_EDGES) atomicAdd(&g_deg[dst[e]], 1);
}
__global__ __launch_bounds__(256) void k_scan_blk() {
    __shared__ int wsum[8];
    const int blk = blockIdx.x, t = threadIdx.x;
    const int base = blk * 1024 + t * 4;
    int v[4], s = 0;
#pragma unroll
    for (int j = 0; j < 4; j++) {
        int i = base + j;
        v[j] = (i < N_NODES) ? g_deg[i] : 0;
        s += v[j];
    }
    const int lane = t & 31, w = t >> 5;
    int ps = s;
#pragma unroll
    for (int o = 1; o < 32; o <<= 1) {
        int y = __shfl_up_sync(0xffffffffu, ps, o);
        if (lane >= o) ps += y;
    }
    if (lane == 31) wsum[w] = ps;
    __syncthreads();
    if (w == 0) {
        int ws = (lane < 8) ? wsum[lane] : 0;
#pragma unroll
        for (int o = 1; o < 8; o <<= 1) {
            int y = __shfl_up_sync(0xffffffffu, ws, o);
            if (lane >= o) ws += y;
        }
        if (lane < 8) wsum[lane] = ws;
    }
    __syncthreads();
    int run = ps - s + (w > 0 ? wsum[w - 1] : 0);
#pragma unroll
    for (int j = 0; j < 4; j++) {
        int i = base + j;
        if (i < N_NODES) g_off[i] = run;
        run += v[j];
    }
    if (t == 255) g_bsum[blk] = wsum[7];
}
__global__ void k_scan_top() {
    const int lane = threadIdx.x;
    const int nblk = (N_NODES + 1023) / 1024;
    int a = (lane < nblk) ? g_bsum[lane] : 0;
    int b = (lane + 32 < nblk) ? g_bsum[lane + 32] : 0;
    int pa = a;
#pragma unroll
    for (int o = 1; o < 32; o <<= 1) {
        int y = __shfl_up_sync(0xffffffffu, pa, o);
        if (lane >= o) pa += y;
    }
    int tot0 = __shfl_sync(0xffffffffu, pa, 31);
    int pb = b;
#pragma unroll
    for (int o = 1; o < 32; o <<= 1) {
        int y = __shfl_up_sync(0xffffffffu, pb, o);
        if (lane >= o) pb += y;
    }
    if (lane < nblk) g_bpre[lane] = pa - a;
    if (lane + 32 < nblk) g_bpre[lane + 32] = tot0 + pb - b;
}
__global__ void k_scan_add() {
    int i = blockIdx.x * blockDim.x + threadIdx.x;
    if (i < N_NODES) {
        int o = g_off[i] + g_bpre[i >> 10];
        g_off[i] = o;
        g_cur[i] = o;
    }
    if (i == 0) g_off[N_NODES] = N_EDGES;
}
__global__ void k_fill(const int* __restrict__ src, const int* __restrict__ dst) {
    int e = blockIdx.x * blockDim.x + threadIdx.x;
    if (e < N_EDGES) {
        int d = dst[e];
        int p = atomicAdd(&g_cur[d], 1);
        g_csr_src[p] = src[e];
    }
}

// ---------------- bf16 splits ------------------------------------------------
__global__ void k_split_x(const float* __restrict__ x) {
    int i = blockIdx.x * blockDim.x + threadIdx.x;
    const int total = N_NODES * NFEAT / 8;
    if (i >= total) return;
    const float4* p = (const float4*)x + (size_t)i * 2;
    float4 v0 = p[0], v1 = p[1];
    float f[8] = {v0.x, v0.y, v0.z, v0.w, v1.x, v1.y, v1.z, v1.w};
    __nv_bfloat16 hi[8], lo[8];
#pragma unroll
    for (int j = 0; j < 8; j++) {
        hi[j] = __float2bfloat16(f[j]);
        lo[j] = __float2bfloat16(f[j] - __bfloat162float(hi[j]));
    }
    *(uint4*)(g_xhi + (size_t)i * 8) = *(uint4*)hi;
    *(uint4*)(g_xlo + (size_t)i * 8) = *(uint4*)lo;
}
__global__ void k_split_w(const float* __restrict__ W1) {
    int idx = blockIdx.x * blockDim.x + threadIdx.x;
    if (idx >= F1 * NFEAT) return;
    int n = idx >> 9, k = idx & 511;
    int h = n >> 6, c = n & 63;
    float w = W1[((size_t)h * NFEAT + k) * NHID + c];
    __nv_bfloat16 hi = __float2bfloat16(w);
    __nv_bfloat16 lo = __float2bfloat16(w - __bfloat162float(hi));
    g_WThi[(size_t)n * NFEAT + k] = hi;
    g_WTlo[(size_t)n * NFEAT + k] = lo;
}
__global__ void k_split_w2(const float* __restrict__ W2) {
    int idx = blockIdx.x * blockDim.x + threadIdx.x;
    if (idx >= N2PAD * F1) return;
    int n = idx >> 9, k = idx & 511;
    float w = (n < NCLASS) ? W2[(size_t)k * NCLASS + n] : 0.f;
    __nv_bfloat16 hi = __float2bfloat16(w);
    __nv_bfloat16 lo = __float2bfloat16(w - __bfloat162float(hi));
    g_W2hi[(size_t)n * F1 + k] = hi;
    g_W2lo[(size_t)n * F1 + k] = lo;
}

// ---------------- GEMM1 (fused-split HMMA): h1 = x @ Wt ---------------------
// Per K-chunk(32) load {A_hi,A_lo,B_hi,B_lo} once; MMA hi*hi + lo*hi + hi*lo.
// CTA 128x128, 8 warps (2m x 4n), warp tile 64x32, 2-stage cp.async pipe,
// 2 CTAs/SM.
#define G1_BM     128
#define G1_BN     128
#define G1_KITER  16                 // 512 / 32
#define G1_ROWB   80
#define G1_REG    10240              // one 128-row x 32-half region
#define G1_STAGE  (4 * G1_REG)       // Ahi|Alo|Bhi|Blo = 40960
#define G1_SMEM   (2 * G1_STAGE)     // 81920

__device__ __forceinline__ void g1_prefetch(int kb, uint32_t stage, int bm, int bn, int t) {
    const int k_in = kb * 32;
#pragma unroll
    for (int i = 0; i < 8; i++) {
        int q = t + i * 256;
        int region = q >> 9;          // 0:Ahi 1:Alo 2:Bhi 3:Blo
        int idx = q & 511;
        int row = idx >> 2, c = idx & 3;
        uint32_t dst = stage + region * G1_REG + row * G1_ROWB + c * 16;
        if (region < 2) {
            int grow = bm + row;
            int ok = grow < N_NODES;
            if (!ok) grow = 0;
            const __nv_bfloat16* Asrc = region ? g_xlo : g_xhi;
            const void* srcp = Asrc + (size_t)grow * NFEAT + k_in + c * 8;
            int sz = ok ? 16 : 0;
            asm volatile("cp.async.cg.shared.global [%0], [%1], 16, %2;"
                         :: "r"(dst), "l"(srcp), "r"(sz));
        } else {
            const __nv_bfloat16* Bsrc = (region == 3) ? g_WTlo : g_WThi;
            const void* srcp = Bsrc + (size_t)(bn + row) * NFEAT + k_in + c * 8;
            asm volatile("cp.async.cg.shared.global [%0], [%1], 16;"
                         :: "r"(dst), "l"(srcp));
        }
    }
}

__global__ __launch_bounds__(256, 2) void k_gemm1_mma() {
    extern __shared__ char dyn[];
    const uint32_t sbase = smem_u32(dyn);
    const int t    = threadIdx.x;
    const int wid  = t >> 5;
    const int lane = t & 31;
    const int bm   = blockIdx.x * G1_BM;
    const int bn   = blockIdx.y * G1_BN;
    const int mw   = (wid >> 2) * 64;
    const int nw   = (wid & 3) * 32;

    float acc[4][4][4];
#pragma unroll
    for (int mt = 0; mt < 4; mt++)
#pragma unroll
        for (int nt = 0; nt < 4; nt++)
#pragma unroll
            for (int j = 0; j < 4; j++) acc[mt][nt][j] = 0.f;

    g1_prefetch(0, sbase, bm, bn, t);
    asm volatile("cp.async.commit_group;");
    g1_prefetch(1, sbase + G1_STAGE, bm, bn, t);
    asm volatile("cp.async.commit_group;");

    const uint32_t a_off = (mw + (lane & 15)) * G1_ROWB + ((lane >> 4) * 16);
    const uint32_t b_off = (nw + (lane & 7) + ((lane >> 4) << 3)) * G1_ROWB + (((lane >> 3) & 1) * 16);

    for (int kb = 0; kb < G1_KITER; kb++) {
        asm volatile("cp.async.wait_group 1;");
        __syncthreads();
        const uint32_t stage = sbase + (kb & 1) * G1_STAGE;

#pragma unroll
        for (int ks = 0; ks < 2; ks++) {
            uint32_t ahi[4][4], alo[4][4];
#pragma unroll
            for (int mt = 0; mt < 4; mt++) {
                uint32_t ad = stage + a_off + mt * (16 * G1_ROWB) + ks * 32;
                LDSM_X4(ahi[mt][0], ahi[mt][1], ahi[mt][2], ahi[mt][3], ad);
                LDSM_X4(alo[mt][0], alo[mt][1], alo[mt][2], alo[mt][3], ad + G1_REG);
            }
            uint32_t b[2][4];
            // --- B_hi: hi*hi and lo*hi ---
#pragma unroll
            for (int np = 0; np < 2; np++) {
                uint32_t bd = stage + 2 * G1_REG + b_off + np * (16 * G1_ROWB) + ks * 32;
                LDSM_X4(b[np][0], b[np][1], b[np][2], b[np][3], bd);
            }
#pragma unroll
            for (int mt = 0; mt < 4; mt++)
#pragma unroll
                for (int nt = 0; nt < 4; nt++) {
                    const uint32_t b0 = b[nt >> 1][(nt & 1) * 2];
                    const uint32_t b1 = b[nt >> 1][(nt & 1) * 2 + 1];
                    MMA16816(acc[mt][nt], ahi[mt], b0, b1);
                    MMA16816(acc[mt][nt], alo[mt], b0, b1);
                }
            // --- B_lo: hi*lo ---
#pragma unroll
            for (int np = 0; np < 2; np++) {
                uint32_t bd = stage + 3 * G1_REG + b_off + np * (16 * G1_ROWB) + ks * 32;
                LDSM_X4(b[np][0], b[np][1], b[np][2], b[np][3], bd);
            }
#pragma unroll
            for (int mt = 0; mt < 4; mt++)
#pragma unroll
                for (int nt = 0; nt < 4; nt++) {
                    const uint32_t b0 = b[nt >> 1][(nt & 1) * 2];
                    const uint32_t b1 = b[nt >> 1][(nt & 1) * 2 + 1];
                    MMA16816(acc[mt][nt], ahi[mt], b0, b1);
                }
        }
        __syncthreads();
        if (kb + 2 < G1_KITER)
            g1_prefetch(kb + 2, stage, bm, bn, t);
        asm volatile("cp.async.commit_group;");
    }

    const int r_base = bm + mw + (lane >> 2);
    const int c_base = bn + nw + (lane & 3) * 2;
#pragma unroll
    for (int mt = 0; mt < 4; mt++) {
#pragma unroll
        for (int nt = 0; nt < 4; nt++) {
            int r0 = r_base + mt * 16;
            int cc = c_base + nt * 8;
            if (r0 < N_NODES)
                *(float2*)(g_h1 + (size_t)r0 * F1 + cc) = make_float2(acc[mt][nt][0], acc[mt][nt][1]);
            if (r0 + 8 < N_NODES)
                *(float2*)(g_h1 + (size_t)(r0 + 8) * F1 + cc) = make_float2(acc[mt][nt][2], acc[mt][nt][3]);
        }
    }
}

// ---------------- GEMM2 (fused-split HMMA): h2 = z @ W2 ---------------------
// CTA 128x64, 8 warps (4m x 2n), warp tile 32x32, 2-stage pipe.
#define G2_BM     128
#define G2_KITER  16
#define G2_AREG   10240              // 128 rows x 80B
#define G2_BREG   5120               // 64 rows x 80B
#define G2_STAGE  (2 * G2_AREG + 2 * G2_BREG)   // 30720
#define G2_SMEM   (2 * G2_STAGE)                // 61440

__device__ __forceinline__ void g2_prefetch(int kb, uint32_t stage, int bm, int t) {
    const int k_in = kb * 32;
#pragma unroll
    for (int i = 0; i < 6; i++) {
        int q = t + i * 256;
        if (q < 1024) {                 // A: 2 regions x 128 rows x 4 chunks
            int region = q >> 9;
            int idx = q & 511;
            int row = idx >> 2, c = idx & 3;
            uint32_t dst = stage + region * G2_AREG + row * G1_ROWB + c * 16;
            int grow = bm + row;
            int ok = grow < N_NODES;
            if (!ok) grow = 0;
            const __nv_bfloat16* Asrc = region ? g_zlo : g_zhi;
            const void* srcp = Asrc + (size_t)grow * F1 + k_in + c * 8;
            int sz = ok ? 16 : 0;
            asm volatile("cp.async.cg.shared.global [%0], [%1], 16, %2;"
                         :: "r"(dst), "l"(srcp), "r"(sz));
        } else {                        // B: 2 regions x 64 rows x 4 chunks
            int qb = q - 1024;
            int region = qb >> 8;
            int idx = qb & 255;
            int row = idx >> 2, c = idx & 3;
            uint32_t dst = stage + 2 * G2_AREG + region * G2_BREG + row * G1_ROWB + c * 16;
            const __nv_bfloat16* Bsrc = region ? g_W2lo : g_W2hi;
            const void* srcp = Bsrc + (size_t)row * F1 + k_in + c * 8;
            asm volatile("cp.async.cg.shared.global [%0], [%1], 16;"
                         :: "r"(dst), "l"(srcp));
        }
    }
}

__global__ __launch_bounds__(256, 2) void k_gemm2_mma() {
    extern __shared__ char dyn[];
    const uint32_t sbase = smem_u32(dyn);
    const int t    = threadIdx.x;
    const int wid  = t >> 5;
    const int lane = t & 31;
    const int bm   = blockIdx.x * G2_BM;
    const int mw   = (wid >> 1) * 32;
    const int nw   = (wid & 1) * 32;

    float acc[2][4][4];
#pragma unroll
    for (int mt = 0; mt < 2; mt++)
#pragma unroll
        for (int nt = 0; nt < 4; nt++)
#pragma unroll
            for (int j = 0; j < 4; j++) acc[mt][nt][j] = 0.f;

    g2_prefetch(0, sbase, bm, t);
    asm volatile("cp.async.commit_group;");
    g2_prefetch(1, sbase + G2_STAGE, bm, t);
    asm volatile("cp.async.commit_group;");

    const uint32_t a_off = (mw + (lane & 15)) * G1_ROWB + ((lane >> 4) * 16);
    const uint32_t b_off = (nw + (lane & 7) + ((lane >> 4) << 3)) * G1_ROWB + (((lane >> 3) & 1) * 16);

    for (int kb = 0; kb < G2_KITER; kb++) {
        asm volatile("cp.async.wait_group 1;");
        __syncthreads();
        const uint32_t stage = sbase + (kb & 1) * G2_STAGE;

#pragma unroll
        for (int ks = 0; ks < 2; ks++) {
            uint32_t ahi[2][4], alo[2][4];
#pragma unroll
            for (int mt = 0; mt < 2; mt++) {
                uint32_t ad = stage + a_off + mt * (16 * G1_ROWB) + ks * 32;
                LDSM_X4(ahi[mt][0], ahi[mt][1], ahi[mt][2], ahi[mt][3], ad);
                LDSM_X4(alo[mt][0], alo[mt][1], alo[mt][2], alo[mt][3], ad + G2_AREG);
            }
            uint32_t b[2][4];
#pragma unroll
            for (int np = 0; np < 2; np++) {
                uint32_t bd = stage + 2 * G2_AREG + b_off + np * (16 * G1_ROWB) + ks * 32;
                LDSM_X4(b[np][0], b[np][1], b[np][2], b[np][3], bd);
            }
#pragma unroll
            for (int mt = 0; mt < 2; mt++)
#pragma unroll
                for (int nt = 0; nt < 4; nt++) {
                    const uint32_t b0 = b[nt >> 1][(nt & 1) * 2];
                    const uint32_t b1 = b[nt >> 1][(nt & 1) * 2 + 1];
                    MMA16816(acc[mt][nt], ahi[mt], b0, b1);
                    MMA16816(acc[mt][nt], alo[mt], b0, b1);
                }
#pragma unroll
            for (int np = 0; np < 2; np++) {
                uint32_t bd = stage + 2 * G2_AREG + G2_BREG + b_off + np * (16 * G1_ROWB) + ks * 32;
                LDSM_X4(b[np][0], b[np][1], b[np][2], b[np][3], bd);
            }
#pragma unroll
            for (int mt = 0; mt < 2; mt++)
#pragma unroll
                for (int nt = 0; nt < 4; nt++) {
                    const uint32_t b0 = b[nt >> 1][(nt & 1) * 2];
                    const uint32_t b1 = b[nt >> 1][(nt & 1) * 2 + 1];
                    MMA16816(acc[mt][nt], ahi[mt], b0, b1);
                }
        }
        __syncthreads();
        if (kb + 2 < G2_KITER)
            g2_prefetch(kb + 2, stage, bm, t);
        asm volatile("cp.async.commit_group;");
    }

    const int r_base = bm + mw + (lane >> 2);
    const int c_base = nw + (lane & 3) * 2;
#pragma unroll
    for (int mt = 0; mt < 2; mt++) {
#pragma unroll
        for (int nt = 0; nt < 4; nt++) {
            int r0 = r_base + mt * 16;
            int cc = c_base + nt * 8;
            if (cc < NCLASS) {
                if (r0 < N_NODES)
                    *(float2*)(g_h2 + (size_t)r0 * NCLASS + cc) = make_float2(acc[mt][nt][0], acc[mt][nt][1]);
                if (r0 + 8 < N_NODES)
                    *(float2*)(g_h2 + (size_t)(r0 + 8) * NCLASS + cc) = make_float2(acc[mt][nt][2], acc[mt][nt][3]);
            }
        }
    }
}

// ---------------- per-node attention scores, layer 1 ------------------------
__global__ void k_scores1(const float* __restrict__ a1) {
    int gw   = (blockIdx.x * blockDim.x + threadIdx.x) >> 5;
    int lane = threadIdx.x & 31;
    if (gw >= N_NODES) return;
    int h  = lane >> 2;
    int cl = (lane & 3) * 16;
    const float4* hp = (const float4*)(g_h1 + (size_t)gw * F1 + lane * 16);
    const float*  as = a1 + h * 128 + cl;
    const float*  ad = a1 + h * 128 + 64 + cl;
    float ss = 0.f, sd = 0.f;
#pragma unroll
    for (int j = 0; j < 4; j++) {
        float4 v = hp[j];
        ss += v.x * as[j * 4 + 0] + v.y * as[j * 4 + 1] + v.z * as[j * 4 + 2] + v.w * as[j * 4 + 3];
        sd += v.x * ad[j * 4 + 0] + v.y * ad[j * 4 + 1] + v.z * ad[j * 4 + 2] + v.w * ad[j * 4 + 3];
    }
    ss += __shfl_xor_sync(0xffffffffu, ss, 1);
    ss += __shfl_xor_sync(0xffffffffu, ss, 2);
    sd += __shfl_xor_sync(0xffffffffu, sd, 1);
    sd += __shfl_xor_sync(0xffffffffu, sd, 2);
    if ((lane & 3) == 0) {
        g_s1s[gw * NHEAD + h] = ss;
        g_s1d[gw * NHEAD + h] = sd;
    }
}

__device__ __forceinline__ float lrelu(float x) { return x > 0.f ? x : NEG * x; }

// ---------------- layer-1 softmax-aggregate (emits split bf16 z) ------------
__global__ __launch_bounds__(256) void k_agg1(const float* __restrict__ b1) {
    int n    = (blockIdx.x * blockDim.x + threadIdx.x) >> 5;
    int lane = threadIdx.x & 31;
    if (n >= N_NODES) return;
    const int beg = g_off[n], end = g_off[n + 1];

    const int h  = lane & 7;
    const int es = lane >> 3;
    const float sdh = g_s1d[n * NHEAD + h];

    float m = -1e30f;
    for (int i = beg + es; i < end; i += 4) {
        int s = g_csr_src[i];
        float e = lrelu(g_s1s[s * NHEAD + h] + sdh);
        m = fmaxf(m, e);
    }
    m = fmaxf(m, __shfl_xor_sync(0xffffffffu, m, 8));
    m = fmaxf(m, __shfl_xor_sync(0xffffffffu, m, 16));

    float den = 0.f;
    for (int i = beg + es; i < end; i += 4) {
        int s = g_csr_src[i];
        float e = lrelu(g_s1s[s * NHEAD + h] + sdh);
        den += __expf(e - m);
    }
    den += __shfl_xor_sync(0xffffffffu, den, 8);
    den += __shfl_xor_sync(0xffffffffu, den, 16);
    den = fmaxf(den, 1e-16f);

    float acc[16];
#pragma unroll
    for (int j = 0; j < 16; j++) acc[j] = 0.f;
    const int hl = lane >> 2;

    for (int i = beg; i < end; i++) {
        int s = g_csr_src[i];
        float alpha = 0.f;
        if (lane < 8) {
            float e = lrelu(g_s1s[s * NHEAD + lane] + sdh);
            alpha = __expf(e - m) / den;
        }
        alpha = __shfl_sync(0xffffffffu, alpha, hl);
        const float4* hp = (const float4*)(g_h1 + (size_t)s * F1 + lane * 16);
#pragma unroll
        for (int j = 0; j < 4; j++) {
            float4 v = hp[j];
            acc[j * 4 + 0] += alpha * v.x;
            acc[j * 4 + 1] += alpha * v.y;
            acc[j * 4 + 2] += alpha * v.z;
            acc[j * 4 + 3] += alpha * v.w;
        }
    }

    const float4* bp = (const float4*)(b1 + lane * 16);
#pragma unroll
    for (int j = 0; j < 4; j++) {
        float4 b = bp[j];
        float v[4];
        v[0] = acc[j * 4 + 0] + b.x;
        v[1] = acc[j * 4 + 1] + b.y;
        v[2] = acc[j * 4 + 2] + b.z;
        v[3] = acc[j * 4 + 3] + b.w;
        __nv_bfloat16 hi[4], lo[4];
#pragma unroll
        for (int q = 0; q < 4; q++) {
            float e = v[q] > 0.f ? v[q] : expm1f(v[q]);
            hi[q] = __float2bfloat16(e);
            lo[q] = __float2bfloat16(e - __bfloat162float(hi[q]));
        }
        *(uint2*)(g_zhi + (size_t)n * F1 + lane * 16 + j * 4) = *(uint2*)hi;
        *(uint2*)(g_zlo + (size_t)n * F1 + lane * 16 + j * 4) = *(uint2*)lo;
    }
}

// ---------------- per-node attention scores, layer 2 ------------------------
__global__ void k_scores2(const float* __restrict__ a2) {
    int gw   = (blockIdx.x * blockDim.x + threadIdx.x) >> 5;
    int lane = threadIdx.x & 31;
    if (gw >= N_NODES) return;
    float v0 = g_h2[(size_t)gw * NCLASS + lane];
    float ss = v0 * a2[lane];
    float sd = v0 * a2[NCLASS + lane];
    if (lane < 8) {
        float v1 = g_h2[(size_t)gw * NCLASS + 32 + lane];
        ss += v1 * a2[32 + lane];
        sd += v1 * a2[NCLASS + 32 + lane];
    }
#pragma unroll
    for (int off = 16; off > 0; off >>= 1) {
        ss += __shfl_xor_sync(0xffffffffu, ss, off);
        sd += __shfl_xor_sync(0xffffffffu, sd, off);
    }
    if (lane == 0) {
        g_s2s[gw] = ss;
        g_s2d[gw] = sd;
    }
}

// ---------------- layer-2 aggregate + bias + log_softmax --------------------
__global__ __launch_bounds__(256) void k_agg2(const float* __restrict__ b2,
                                              float* __restrict__ out) {
    int n    = (blockIdx.x * blockDim.x + threadIdx.x) >> 5;
    int lane = threadIdx.x & 31;
    if (n >= N_NODES) return;
    const int beg = g_off[n], end = g_off[n + 1];
    const float sdn = g_s2d[n];

    float m = -1e30f;
    for (int i = beg + lane; i < end; i += 32) {
        int s = g_csr_src[i];
        m = fmaxf(m, lrelu(g_s2s[s] + sdn));
    }
#pragma unroll
    for (int off = 16; off > 0; off >>= 1)
        m = fmaxf(m, __shfl_xor_sync(0xffffffffu, m, off));

    float den = 0.f;
    for (int i = beg + lane; i < end; i += 32) {
        int s = g_csr_src[i];
        den += __expf(lrelu(g_s2s[s] + sdn) - m);
    }
#pragma unroll
    for (int off = 16; off > 0; off >>= 1)
        den += __shfl_xor_sync(0xffffffffu, den, off);
    den = fmaxf(den, 1e-16f);

    float acc0 = 0.f, acc1 = 0.f;
    for (int i = beg; i < end; i++) {
        int s = g_csr_src[i];
        float e = lrelu(g_s2s[s] + sdn);
        float alpha = __expf(e - m) / den;
        acc0 += alpha * g_h2[(size_t)s * NCLASS + lane];
        if (lane < 8) acc1 += alpha * g_h2[(size_t)s * NCLASS + 32 + lane];
    }

    float v0 = acc0 + b2[lane];
    float v1 = (lane < 8) ? (acc1 + b2[32 + lane]) : -1e30f;

    float mx = fmaxf(v0, v1);
#pragma unroll
    for (int off = 16; off > 0; off >>= 1)
        mx = fmaxf(mx, __shfl_xor_sync(0xffffffffu, mx, off));
    float se = __expf(v0 - mx) + ((lane < 8) ? __expf(v1 - mx) : 0.f);
#pragma unroll
    for (int off = 16; off > 0; off >>= 1)
        se += __shfl_xor_sync(0xffffffffu, se, off);
    float ls = logf(se);

    out[(size_t)n * NCLASS + lane] = v0 - mx - ls;
    if (lane < 8) out[(size_t)n * NCLASS + 32 + lane] = v1 - mx - ls;
}

// ---------------- launch -----------------------------------------------------
extern "C" void kernel_launch(void* const* d_in, const int* in_sizes, int n_in,
                              void* d_out, int out_size) {
    const float* x  = (const float*)d_in[0];
    const int*   el = (const int*)d_in[1];
    const float* W1 = (const float*)d_in[2];
    const float* a1 = (const float*)d_in[3];
    const float* b1 = (const float*)d_in[4];
    const float* W2 = (const float*)d_in[5];
    const float* a2 = (const float*)d_in[6];
    const float* b2 = (const float*)d_in[7];
    float* out = (float*)d_out;

    const int* src = el;
    const int* dst = el + N_EDGES;

    cudaFuncSetAttribute(k_gemm1_mma, cudaFuncAttributeMaxDynamicSharedMemorySize, G1_SMEM);
    cudaFuncSetAttribute(k_gemm2_mma, cudaFuncAttributeMaxDynamicSharedMemorySize, G2_SMEM);

    const int TB = 256;
    const int NBLK = (N_NODES + 1023) / 1024;

    // launch index 3 (the ncu-profiled slot) is gemm1
    k_split_x<<<(N_NODES * NFEAT / 8 + TB - 1) / TB, TB>>>(x);          // 0
    k_split_w<<<(F1 * NFEAT + TB - 1) / TB, TB>>>(W1);                  // 1
    k_zero_deg<<<(N_NODES + TB - 1) / TB, TB>>>();                      // 2
    k_gemm1_mma<<<dim3((N_NODES + G1_BM - 1) / G1_BM, F1 / G1_BN), 256, G1_SMEM>>>(); // 3
    k_split_w2<<<(N2PAD * F1 + TB - 1) / TB, TB>>>(W2);                 // 4
    k_count<<<(N_EDGES + TB - 1) / TB, TB>>>(dst);                      // 5
    k_scan_blk<<<NBLK, 256>>>();                                        // 6
    k_scan_top<<<1, 32>>>();                                            // 7
    k_scan_add<<<(N_NODES + TB - 1) / TB, TB>>>();                      // 8
    k_fill<<<(N_EDGES + TB - 1) / TB, TB>>>(src, dst);                  // 9
    k_scores1<<<(N_NODES + 7) / 8, 256>>>(a1);                          // 10
    k_agg1<<<(N_NODES + 7) / 8, 256>>>(b1);                             // 11
    k_gemm2_mma<<<(N_NODES + G2_BM - 1) / G2_BM, 256, G2_SMEM>>>();     // 12
    k_scores2<<<(N_NODES + 7) / 8, 256>>>(a2);                          // 13
    k_agg2<<<(N_NODES + 7) / 8, 256>>>(b2, out);                        // 14
}

// round 8
// speedup vs baseline: 1.8573x; 1.1349x over previous
#include <cuda_runtime.h>
#include <cuda_bf16.h>
#include <cuda_fp16.h>
#include <cstdint>

#define N_NODES 50000
#define N_EDGES 800000
#define NFEAT   512
#define NHID    64
#define NHEAD   8
#define F1      512      // NHEAD*NHID
#define NCLASS  40
#define N2PAD   64
#define NEG     0.2f

// ---------------- scratch ---------------------------------------------------
__device__ float g_h1[(size_t)N_NODES * F1];
__device__ __half g_h1h[(size_t)N_NODES * F1];   // fp16 gather copy of h1
__device__ float g_h2[(size_t)N_NODES * NCLASS];
__device__ float g_s1s[N_NODES * NHEAD];
__device__ float g_s1d[N_NODES * NHEAD];
__device__ float g_s2s[N_NODES];
__device__ float g_s2d[N_NODES];
__device__ int   g_deg[N_NODES];
__device__ int   g_off[N_NODES + 1];
__device__ int   g_cur[N_NODES];
__device__ int   g_csr_src[N_EDGES];
__device__ int   g_bsum[64];
__device__ int   g_bpre[64];
// bf16 split operands
__device__ __nv_bfloat16 g_xhi[(size_t)N_NODES * NFEAT];
__device__ __nv_bfloat16 g_xlo[(size_t)N_NODES * NFEAT];
__device__ __nv_bfloat16 g_WThi[F1 * NFEAT];   // [n][k], n = h*64+c
__device__ __nv_bfloat16 g_WTlo[F1 * NFEAT];
__device__ __nv_bfloat16 g_zhi[(size_t)N_NODES * F1];   // layer-2 input, split
__device__ __nv_bfloat16 g_zlo[(size_t)N_NODES * F1];
__device__ __nv_bfloat16 g_W2hi[N2PAD * F1];   // [n][k], n padded to 64
__device__ __nv_bfloat16 g_W2lo[N2PAD * F1];

__device__ __forceinline__ uint32_t smem_u32(const void* p) {
    uint32_t a;
    asm("{ .reg .u64 t; cvta.to.shared.u64 t, %1; cvt.u32.u64 %0, t; }" : "=r"(a) : "l"(p));
    return a;
}

#define LDSM_X4(r0, r1, r2, r3, addr) \
    asm volatile("ldmatrix.sync.aligned.m8n8.x4.shared.b16 {%0,%1,%2,%3}, [%4];" \
                 : "=r"(r0), "=r"(r1), "=r"(r2), "=r"(r3) : "r"(addr))
#define MMA16816(acc, a, b0, b1) \
    asm volatile("mma.sync.aligned.m16n8k16.row.col.f32.bf16.bf16.f32 " \
                 "{%0,%1,%2,%3}, {%4,%5,%6,%7}, {%8,%9}, {%0,%1,%2,%3};" \
                 : "+f"((acc)[0]), "+f"((acc)[1]), "+f"((acc)[2]), "+f"((acc)[3]) \
                 : "r"((a)[0]), "r"((a)[1]), "r"((a)[2]), "r"((a)[3]), "r"(b0), "r"(b1))

// ---------------- CSR construction ------------------------------------------
__global__ void k_zero_deg() {
    int i = blockIdx.x * blockDim.x + threadIdx.x;
    if (i < N_NODES) g_deg[i] = 0;
}
__global__ void k_count(const int* __restrict__ dst) {
    int e = blockIdx.x * blockDim.x + threadIdx.x;
    if (e < N_EDGES) atomicAdd(&g_deg[dst[e]], 1);
}
__global__ __launch_bounds__(256) void k_scan_blk() {
    __shared__ int wsum[8];
    const int blk = blockIdx.x, t = threadIdx.x;
    const int base = blk * 1024 + t * 4;
    int v[4], s = 0;
#pragma unroll
    for (int j = 0; j < 4; j++) {
        int i = base + j;
        v[j] = (i < N_NODES) ? g_deg[i] : 0;
        s += v[j];
    }
    const int lane = t & 31, w = t >> 5;
    int ps = s;
#pragma unroll
    for (int o = 1; o < 32; o <<= 1) {
        int y = __shfl_up_sync(0xffffffffu, ps, o);
        if (lane >= o) ps += y;
    }
    if (lane == 31) wsum[w] = ps;
    __syncthreads();
    if (w == 0) {
        int ws = (lane < 8) ? wsum[lane] : 0;
#pragma unroll
        for (int o = 1; o < 8; o <<= 1) {
            int y = __shfl_up_sync(0xffffffffu, ws, o);
            if (lane >= o) ws += y;
        }
        if (lane < 8) wsum[lane] = ws;
    }
    __syncthreads();
    int run = ps - s + (w > 0 ? wsum[w - 1] : 0);
#pragma unroll
    for (int j = 0; j < 4; j++) {
        int i = base + j;
        if (i < N_NODES) g_off[i] = run;
        run += v[j];
    }
    if (t == 255) g_bsum[blk] = wsum[7];
}
__global__ void k_scan_top() {
    const int lane = threadIdx.x;
    const int nblk = (N_NODES + 1023) / 1024;
    int a = (lane < nblk) ? g_bsum[lane] : 0;
    int b = (lane + 32 < nblk) ? g_bsum[lane + 32] : 0;
    int pa = a;
#pragma unroll
    for (int o = 1; o < 32; o <<= 1) {
        int y = __shfl_up_sync(0xffffffffu, pa, o);
        if (lane >= o) pa += y;
    }
    int tot0 = __shfl_sync(0xffffffffu, pa, 31);
    int pb = b;
#pragma unroll
    for (int o = 1; o < 32; o <<= 1) {
        int y = __shfl_up_sync(0xffffffffu, pb, o);
        if (lane >= o) pb += y;
    }
    if (lane < nblk) g_bpre[lane] = pa - a;
    if (lane + 32 < nblk) g_bpre[lane + 32] = tot0 + pb - b;
}
__global__ void k_scan_add() {
    int i = blockIdx.x * blockDim.x + threadIdx.x;
    if (i < N_NODES) {
        int o = g_off[i] + g_bpre[i >> 10];
        g_off[i] = o;
        g_cur[i] = o;
    }
    if (i == 0) g_off[N_NODES] = N_EDGES;
}
__global__ void k_fill(const int* __restrict__ src, const int* __restrict__ dst) {
    int e = blockIdx.x * blockDim.x + threadIdx.x;
    if (e < N_EDGES) {
        int d = dst[e];
        int p = atomicAdd(&g_cur[d], 1);
        g_csr_src[p] = src[e];
    }
}

// ---------------- bf16 splits ------------------------------------------------
__global__ void k_split_x(const float* __restrict__ x) {
    int i = blockIdx.x * blockDim.x + threadIdx.x;
    const int total = N_NODES * NFEAT / 8;
    if (i >= total) return;
    const float4* p = (const float4*)x + (size_t)i * 2;
    float4 v0 = p[0], v1 = p[1];
    float f[8] = {v0.x, v0.y, v0.z, v0.w, v1.x, v1.y, v1.z, v1.w};
    __nv_bfloat16 hi[8], lo[8];
#pragma unroll
    for (int j = 0; j < 8; j++) {
        hi[j] = __float2bfloat16(f[j]);
        lo[j] = __float2bfloat16(f[j] - __bfloat162float(hi[j]));
    }
    *(uint4*)(g_xhi + (size_t)i * 8) = *(uint4*)hi;
    *(uint4*)(g_xlo + (size_t)i * 8) = *(uint4*)lo;
}
__global__ void k_split_w(const float* __restrict__ W1) {
    int idx = blockIdx.x * blockDim.x + threadIdx.x;
    if (idx >= F1 * NFEAT) return;
    int n = idx >> 9, k = idx & 511;
    int h = n >> 6, c = n & 63;
    float w = W1[((size_t)h * NFEAT + k) * NHID + c];
    __nv_bfloat16 hi = __float2bfloat16(w);
    __nv_bfloat16 lo = __float2bfloat16(w - __bfloat162float(hi));
    g_WThi[(size_t)n * NFEAT + k] = hi;
    g_WTlo[(size_t)n * NFEAT + k] = lo;
}
__global__ void k_split_w2(const float* __restrict__ W2) {
    int idx = blockIdx.x * blockDim.x + threadIdx.x;
    if (idx >= N2PAD * F1) return;
    int n = idx >> 9, k = idx & 511;
    float w = (n < NCLASS) ? W2[(size_t)k * NCLASS + n] : 0.f;
    __nv_bfloat16 hi = __float2bfloat16(w);
    __nv_bfloat16 lo = __float2bfloat16(w - __bfloat162float(hi));
    g_W2hi[(size_t)n * F1 + k] = hi;
    g_W2lo[(size_t)n * F1 + k] = lo;
}

// ---------------- GEMM1 (fused-split HMMA): h1 = x @ Wt ---------------------
#define G1_BM     128
#define G1_BN     128
#define G1_KITER  16                 // 512 / 32
#define G1_ROWB   80
#define G1_REG    10240
#define G1_STAGE  (4 * G1_REG)       // 40960
#define G1_SMEM   (2 * G1_STAGE)     // 81920

__device__ __forceinline__ void g1_prefetch(int kb, uint32_t stage, int bm, int bn, int t) {
    const int k_in = kb * 32;
#pragma unroll
    for (int i = 0; i < 8; i++) {
        int q = t + i * 256;
        int region = q >> 9;          // 0:Ahi 1:Alo 2:Bhi 3:Blo
        int idx = q & 511;
        int row = idx >> 2, c = idx & 3;
        uint32_t dst = stage + region * G1_REG + row * G1_ROWB + c * 16;
        if (region < 2) {
            int grow = bm + row;
            int ok = grow < N_NODES;
            if (!ok) grow = 0;
            const __nv_bfloat16* Asrc = region ? g_xlo : g_xhi;
            const void* srcp = Asrc + (size_t)grow * NFEAT + k_in + c * 8;
            int sz = ok ? 16 : 0;
            asm volatile("cp.async.cg.shared.global [%0], [%1], 16, %2;"
                         :: "r"(dst), "l"(srcp), "r"(sz));
        } else {
            const __nv_bfloat16* Bsrc = (region == 3) ? g_WTlo : g_WThi;
            const void* srcp = Bsrc + (size_t)(bn + row) * NFEAT + k_in + c * 8;
            asm volatile("cp.async.cg.shared.global [%0], [%1], 16;"
                         :: "r"(dst), "l"(srcp));
        }
    }
}

__global__ __launch_bounds__(256, 2) void k_gemm1_mma() {
    extern __shared__ char dyn[];
    const uint32_t sbase = smem_u32(dyn);
    const int t    = threadIdx.x;
    const int wid  = t >> 5;
    const int lane = t & 31;
    const int bm   = blockIdx.x * G1_BM;
    const int bn   = blockIdx.y * G1_BN;
    const int mw   = (wid >> 2) * 64;
    const int nw   = (wid & 3) * 32;

    float acc[4][4][4];
#pragma unroll
    for (int mt = 0; mt < 4; mt++)
#pragma unroll
        for (int nt = 0; nt < 4; nt++)
#pragma unroll
            for (int j = 0; j < 4; j++) acc[mt][nt][j] = 0.f;

    g1_prefetch(0, sbase, bm, bn, t);
    asm volatile("cp.async.commit_group;");
    g1_prefetch(1, sbase + G1_STAGE, bm, bn, t);
    asm volatile("cp.async.commit_group;");

    const uint32_t a_off = (mw + (lane & 15)) * G1_ROWB + ((lane >> 4) * 16);
    const uint32_t b_off = (nw + (lane & 7) + ((lane >> 4) << 3)) * G1_ROWB + (((lane >> 3) & 1) * 16);

    for (int kb = 0; kb < G1_KITER; kb++) {
        asm volatile("cp.async.wait_group 1;");
        __syncthreads();
        const uint32_t stage = sbase + (kb & 1) * G1_STAGE;

#pragma unroll
        for (int ks = 0; ks < 2; ks++) {
            uint32_t ahi[4][4], alo[4][4];
#pragma unroll
            for (int mt = 0; mt < 4; mt++) {
                uint32_t ad = stage + a_off + mt * (16 * G1_ROWB) + ks * 32;
                LDSM_X4(ahi[mt][0], ahi[mt][1], ahi[mt][2], ahi[mt][3], ad);
                LDSM_X4(alo[mt][0], alo[mt][1], alo[mt][2], alo[mt][3], ad + G1_REG);
            }
            uint32_t b[2][4];
#pragma unroll
            for (int np = 0; np < 2; np++) {
                uint32_t bd = stage + 2 * G1_REG + b_off + np * (16 * G1_ROWB) + ks * 32;
                LDSM_X4(b[np][0], b[np][1], b[np][2], b[np][3], bd);
            }
#pragma unroll
            for (int mt = 0; mt < 4; mt++)
#pragma unroll
                for (int nt = 0; nt < 4; nt++) {
                    const uint32_t b0 = b[nt >> 1][(nt & 1) * 2];
                    const uint32_t b1 = b[nt >> 1][(nt & 1) * 2 + 1];
                    MMA16816(acc[mt][nt], ahi[mt], b0, b1);
                    MMA16816(acc[mt][nt], alo[mt], b0, b1);
                }
#pragma unroll
            for (int np = 0; np < 2; np++) {
                uint32_t bd = stage + 3 * G1_REG + b_off + np * (16 * G1_ROWB) + ks * 32;
                LDSM_X4(b[np][0], b[np][1], b[np][2], b[np][3], bd);
            }
#pragma unroll
            for (int mt = 0; mt < 4; mt++)
#pragma unroll
                for (int nt = 0; nt < 4; nt++) {
                    const uint32_t b0 = b[nt >> 1][(nt & 1) * 2];
                    const uint32_t b1 = b[nt >> 1][(nt & 1) * 2 + 1];
                    MMA16816(acc[mt][nt], ahi[mt], b0, b1);
                }
        }
        __syncthreads();
        if (kb + 2 < G1_KITER)
            g1_prefetch(kb + 2, stage, bm, bn, t);
        asm volatile("cp.async.commit_group;");
    }

    // epilogue: fp32 h1 (for scores) + fp16 h1h (for aggregation gather)
    const int r_base = bm + mw + (lane >> 2);
    const int c_base = bn + nw + (lane & 3) * 2;
#pragma unroll
    for (int mt = 0; mt < 4; mt++) {
#pragma unroll
        for (int nt = 0; nt < 4; nt++) {
            int r0 = r_base + mt * 16;
            int cc = c_base + nt * 8;
            if (r0 < N_NODES) {
                *(float2*)(g_h1 + (size_t)r0 * F1 + cc) = make_float2(acc[mt][nt][0], acc[mt][nt][1]);
                *(__half2*)(g_h1h + (size_t)r0 * F1 + cc) = __floats2half2_rn(acc[mt][nt][0], acc[mt][nt][1]);
            }
            if (r0 + 8 < N_NODES) {
                *(float2*)(g_h1 + (size_t)(r0 + 8) * F1 + cc) = make_float2(acc[mt][nt][2], acc[mt][nt][3]);
                *(__half2*)(g_h1h + (size_t)(r0 + 8) * F1 + cc) = __floats2half2_rn(acc[mt][nt][2], acc[mt][nt][3]);
            }
        }
    }
}

// ---------------- GEMM2 (fused-split HMMA): h2 = z @ W2 ---------------------
#define G2_BM     128
#define G2_KITER  16
#define G2_AREG   10240
#define G2_BREG   5120
#define G2_STAGE  (2 * G2_AREG + 2 * G2_BREG)   // 30720
#define G2_SMEM   (2 * G2_STAGE)                // 61440

__device__ __forceinline__ void g2_prefetch(int kb, uint32_t stage, int bm, int t) {
    const int k_in = kb * 32;
#pragma unroll
    for (int i = 0; i < 6; i++) {
        int q = t + i * 256;
        if (q < 1024) {
            int region = q >> 9;
            int idx = q & 511;
            int row = idx >> 2, c = idx & 3;
            uint32_t dst = stage + region * G2_AREG + row * G1_ROWB + c * 16;
            int grow = bm + row;
            int ok = grow < N_NODES;
            if (!ok) grow = 0;
            const __nv_bfloat16* Asrc = region ? g_zlo : g_zhi;
            const void* srcp = Asrc + (size_t)grow * F1 + k_in + c * 8;
            int sz = ok ? 16 : 0;
            asm volatile("cp.async.cg.shared.global [%0], [%1], 16, %2;"
                         :: "r"(dst), "l"(srcp), "r"(sz));
        } else {
            int qb = q - 1024;
            int region = qb >> 8;
            int idx = qb & 255;
            int row = idx >> 2, c = idx & 3;
            uint32_t dst = stage + 2 * G2_AREG + region * G2_BREG + row * G1_ROWB + c * 16;
            const __nv_bfloat16* Bsrc = region ? g_W2lo : g_W2hi;
            const void* srcp = Bsrc + (size_t)row * F1 + k_in + c * 8;
            asm volatile("cp.async.cg.shared.global [%0], [%1], 16;"
                         :: "r"(dst), "l"(srcp));
        }
    }
}

__global__ __launch_bounds__(256, 2) void k_gemm2_mma() {
    extern __shared__ char dyn[];
    const uint32_t sbase = smem_u32(dyn);
    const int t    = threadIdx.x;
    const int wid  = t >> 5;
    const int lane = t & 31;
    const int bm   = blockIdx.x * G2_BM;
    const int mw   = (wid >> 1) * 32;
    const int nw   = (wid & 1) * 32;

    float acc[2][4][4];
#pragma unroll
    for (int mt = 0; mt < 2; mt++)
#pragma unroll
        for (int nt = 0; nt < 4; nt++)
#pragma unroll
            for (int j = 0; j < 4; j++) acc[mt][nt][j] = 0.f;

    g2_prefetch(0, sbase, bm, t);
    asm volatile("cp.async.commit_group;");
    g2_prefetch(1, sbase + G2_STAGE, bm, t);
    asm volatile("cp.async.commit_group;");

    const uint32_t a_off = (mw + (lane & 15)) * G1_ROWB + ((lane >> 4) * 16);
    const uint32_t b_off = (nw + (lane & 7) + ((lane >> 4) << 3)) * G1_ROWB + (((lane >> 3) & 1) * 16);

    for (int kb = 0; kb < G2_KITER; kb++) {
        asm volatile("cp.async.wait_group 1;");
        __syncthreads();
        const uint32_t stage = sbase + (kb & 1) * G2_STAGE;

#pragma unroll
        for (int ks = 0; ks < 2; ks++) {
            uint32_t ahi[2][4], alo[2][4];
#pragma unroll
            for (int mt = 0; mt < 2; mt++) {
                uint32_t ad = stage + a_off + mt * (16 * G1_ROWB) + ks * 32;
                LDSM_X4(ahi[mt][0], ahi[mt][1], ahi[mt][2], ahi[mt][3], ad);
                LDSM_X4(alo[mt][0], alo[mt][1], alo[mt][2], alo[mt][3], ad + G2_AREG);
            }
            uint32_t b[2][4];
#pragma unroll
            for (int np = 0; np < 2; np++) {
                uint32_t bd = stage + 2 * G2_AREG + b_off + np * (16 * G1_ROWB) + ks * 32;
                LDSM_X4(b[np][0], b[np][1], b[np][2], b[np][3], bd);
            }
#pragma unroll
            for (int mt = 0; mt < 2; mt++)
#pragma unroll
                for (int nt = 0; nt < 4; nt++) {
                    const uint32_t b0 = b[nt >> 1][(nt & 1) * 2];
                    const uint32_t b1 = b[nt >> 1][(nt & 1) * 2 + 1];
                    MMA16816(acc[mt][nt], ahi[mt], b0, b1);
                    MMA16816(acc[mt][nt], alo[mt], b0, b1);
                }
#pragma unroll
            for (int np = 0; np < 2; np++) {
                uint32_t bd = stage + 2 * G2_AREG + G2_BREG + b_off + np * (16 * G1_ROWB) + ks * 32;
                LDSM_X4(b[np][0], b[np][1], b[np][2], b[np][3], bd);
            }
#pragma unroll
            for (int mt = 0; mt < 2; mt++)
#pragma unroll
                for (int nt = 0; nt < 4; nt++) {
                    const uint32_t b0 = b[nt >> 1][(nt & 1) * 2];
                    const uint32_t b1 = b[nt >> 1][(nt & 1) * 2 + 1];
                    MMA16816(acc[mt][nt], ahi[mt], b0, b1);
                }
        }
        __syncthreads();
        if (kb + 2 < G2_KITER)
            g2_prefetch(kb + 2, stage, bm, t);
        asm volatile("cp.async.commit_group;");
    }

    const int r_base = bm + mw + (lane >> 2);
    const int c_base = nw + (lane & 3) * 2;
#pragma unroll
    for (int mt = 0; mt < 2; mt++) {
#pragma unroll
        for (int nt = 0; nt < 4; nt++) {
            int r0 = r_base + mt * 16;
            int cc = c_base + nt * 8;
            if (cc < NCLASS) {
                if (r0 < N_NODES)
                    *(float2*)(g_h2 + (size_t)r0 * NCLASS + cc) = make_float2(acc[mt][nt][0], acc[mt][nt][1]);
                if (r0 + 8 < N_NODES)
                    *(float2*)(g_h2 + (size_t)(r0 + 8) * NCLASS + cc) = make_float2(acc[mt][nt][2], acc[mt][nt][3]);
            }
        }
    }
}

// ---------------- per-node attention scores, layer 1 ------------------------
__global__ void k_scores1(const float* __restrict__ a1) {
    int gw   = (blockIdx.x * blockDim.x + threadIdx.x) >> 5;
    int lane = threadIdx.x & 31;
    if (gw >= N_NODES) return;
    int h  = lane >> 2;
    int cl = (lane & 3) * 16;
    const float4* hp = (const float4*)(g_h1 + (size_t)gw * F1 + lane * 16);
    const float*  as = a1 + h * 128 + cl;
    const float*  ad = a1 + h * 128 + 64 + cl;
    float ss = 0.f, sd = 0.f;
#pragma unroll
    for (int j = 0; j < 4; j++) {
        float4 v = hp[j];
        ss += v.x * as[j * 4 + 0] + v.y * as[j * 4 + 1] + v.z * as[j * 4 + 2] + v.w * as[j * 4 + 3];
        sd += v.x * ad[j * 4 + 0] + v.y * ad[j * 4 + 1] + v.z * ad[j * 4 + 2] + v.w * ad[j * 4 + 3];
    }
    ss += __shfl_xor_sync(0xffffffffu, ss, 1);
    ss += __shfl_xor_sync(0xffffffffu, ss, 2);
    sd += __shfl_xor_sync(0xffffffffu, sd, 1);
    sd += __shfl_xor_sync(0xffffffffu, sd, 2);
    if ((lane & 3) == 0) {
        g_s1s[gw * NHEAD + h] = ss;
        g_s1d[gw * NHEAD + h] = sd;
    }
}

__device__ __forceinline__ float lrelu(float x) { return x > 0.f ? x : NEG * x; }

// ---------------- layer-1 softmax-aggregate (fp16 gather, split bf16 out) ---
__global__ __launch_bounds__(256) void k_agg1(const float* __restrict__ b1) {
    int n    = (blockIdx.x * blockDim.x + threadIdx.x) >> 5;
    int lane = threadIdx.x & 31;
    if (n >= N_NODES) return;
    const int beg = g_off[n], end = g_off[n + 1];

    const int h  = lane & 7;
    const int es = lane >> 3;
    const float sdh = g_s1d[n * NHEAD + h];

    float m = -1e30f;
    for (int i = beg + es; i < end; i += 4) {
        int s = g_csr_src[i];
        float e = lrelu(g_s1s[s * NHEAD + h] + sdh);
        m = fmaxf(m, e);
    }
    m = fmaxf(m, __shfl_xor_sync(0xffffffffu, m, 8));
    m = fmaxf(m, __shfl_xor_sync(0xffffffffu, m, 16));

    float den = 0.f;
    for (int i = beg + es; i < end; i += 4) {
        int s = g_csr_src[i];
        float e = lrelu(g_s1s[s * NHEAD + h] + sdh);
        den += __expf(e - m);
    }
    den += __shfl_xor_sync(0xffffffffu, den, 8);
    den += __shfl_xor_sync(0xffffffffu, den, 16);
    den = fmaxf(den, 1e-16f);

    float acc[16];
#pragma unroll
    for (int j = 0; j < 16; j++) acc[j] = 0.f;
    const int hl = lane >> 2;

    for (int i = beg; i < end; i++) {
        int s = g_csr_src[i];
        float alpha = 0.f;
        if (lane < 8) {
            float e = lrelu(g_s1s[s * NHEAD + lane] + sdh);
            alpha = __expf(e - m) / den;
        }
        alpha = __shfl_sync(0xffffffffu, alpha, hl);
        const uint4* hp = (const uint4*)(g_h1h + (size_t)s * F1 + lane * 16);
        uint4 q0 = hp[0];      // 8 halves
        uint4 q1 = hp[1];      // 8 halves
        float2 f;
        f = __half22float2(*(__half2*)&q0.x); acc[0] += alpha * f.x; acc[1] += alpha * f.y;
        f = __half22float2(*(__half2*)&q0.y); acc[2] += alpha * f.x; acc[3] += alpha * f.y;
        f = __half22float2(*(__half2*)&q0.z); acc[4] += alpha * f.x; acc[5] += alpha * f.y;
        f = __half22float2(*(__half2*)&q0.w); acc[6] += alpha * f.x; acc[7] += alpha * f.y;
        f = __half22float2(*(__half2*)&q1.x); acc[8] += alpha * f.x; acc[9] += alpha * f.y;
        f = __half22float2(*(__half2*)&q1.y); acc[10] += alpha * f.x; acc[11] += alpha * f.y;
        f = __half22float2(*(__half2*)&q1.z); acc[12] += alpha * f.x; acc[13] += alpha * f.y;
        f = __half22float2(*(__half2*)&q1.w); acc[14] += alpha * f.x; acc[15] += alpha * f.y;
    }

    const float4* bp = (const float4*)(b1 + lane * 16);
#pragma unroll
    for (int j = 0; j < 4; j++) {
        float4 b = bp[j];
        float v[4];
        v[0] = acc[j * 4 + 0] + b.x;
        v[1] = acc[j * 4 + 1] + b.y;
        v[2] = acc[j * 4 + 2] + b.z;
        v[3] = acc[j * 4 + 3] + b.w;
        __nv_bfloat16 hi[4], lo[4];
#pragma unroll
        for (int q = 0; q < 4; q++) {
            float e = v[q] > 0.f ? v[q] : expm1f(v[q]);
            hi[q] = __float2bfloat16(e);
            lo[q] = __float2bfloat16(e - __bfloat162float(hi[q]));
        }
        *(uint2*)(g_zhi + (size_t)n * F1 + lane * 16 + j * 4) = *(uint2*)hi;
        *(uint2*)(g_zlo + (size_t)n * F1 + lane * 16 + j * 4) = *(uint2*)lo;
    }
}

// ---------------- per-node attention scores, layer 2 ------------------------
__global__ void k_scores2(const float* __restrict__ a2) {
    int gw   = (blockIdx.x * blockDim.x + threadIdx.x) >> 5;
    int lane = threadIdx.x & 31;
    if (gw >= N_NODES) return;
    float v0 = g_h2[(size_t)gw * NCLASS + lane];
    float ss = v0 * a2[lane];
    float sd = v0 * a2[NCLASS + lane];
    if (lane < 8) {
        float v1 = g_h2[(size_t)gw * NCLASS + 32 + lane];
        ss += v1 * a2[32 + lane];
        sd += v1 * a2[NCLASS + 32 + lane];
    }
#pragma unroll
    for (int off = 16; off > 0; off >>= 1) {
        ss += __shfl_xor_sync(0xffffffffu, ss, off);
        sd += __shfl_xor_sync(0xffffffffu, sd, off);
    }
    if (lane == 0) {
        g_s2s[gw] = ss;
        g_s2d[gw] = sd;
    }
}

// ---------------- layer-2 aggregate + bias + log_softmax --------------------
__global__ __launch_bounds__(256) void k_agg2(const float* __restrict__ b2,
                                              float* __restrict__ out) {
    int n    = (blockIdx.x * blockDim.x + threadIdx.x) >> 5;
    int lane = threadIdx.x & 31;
    if (n >= N_NODES) return;
    const int beg = g_off[n], end = g_off[n + 1];
    const float sdn = g_s2d[n];

    float m = -1e30f;
    for (int i = beg + lane; i < end; i += 32) {
        int s = g_csr_src[i];
        m = fmaxf(m, lrelu(g_s2s[s] + sdn));
    }
#pragma unroll
    for (int off = 16; off > 0; off >>= 1)
        m = fmaxf(m, __shfl_xor_sync(0xffffffffu, m, off));

    float den = 0.f;
    for (int i = beg + lane; i < end; i += 32) {
        int s = g_csr_src[i];
        den += __expf(lrelu(g_s2s[s] + sdn) - m);
    }
#pragma unroll
    for (int off = 16; off > 0; off >>= 1)
        den += __shfl_xor_sync(0xffffffffu, den, off);
    den = fmaxf(den, 1e-16f);

    float acc0 = 0.f, acc1 = 0.f;
    for (int i = beg; i < end; i++) {
        int s = g_csr_src[i];
        float e = lrelu(g_s2s[s] + sdn);
        float alpha = __expf(e - m) / den;
        acc0 += alpha * g_h2[(size_t)s * NCLASS + lane];
        if (lane < 8) acc1 += alpha * g_h2[(size_t)s * NCLASS + 32 + lane];
    }

    float v0 = acc0 + b2[lane];
    float v1 = (lane < 8) ? (acc1 + b2[32 + lane]) : -1e30f;

    float mx = fmaxf(v0, v1);
#pragma unroll
    for (int off = 16; off > 0; off >>= 1)
        mx = fmaxf(mx, __shfl_xor_sync(0xffffffffu, mx, off));
    float se = __expf(v0 - mx) + ((lane < 8) ? __expf(v1 - mx) : 0.f);
#pragma unroll
    for (int off = 16; off > 0; off >>= 1)
        se += __shfl_xor_sync(0xffffffffu, se, off);
    float ls = logf(se);

    out[(size_t)n * NCLASS + lane] = v0 - mx - ls;
    if (lane < 8) out[(size_t)n * NCLASS + 32 + lane] = v1 - mx - ls;
}

// ---------------- launch -----------------------------------------------------
extern "C" void kernel_launch(void* const* d_in, const int* in_sizes, int n_in,
                              void* d_out, int out_size) {
    const float* x  = (const float*)d_in[0];
    const int*   el = (const int*)d_in[1];
    const float* W1 = (const float*)d_in[2];
    const float* a1 = (const float*)d_in[3];
    const float* b1 = (const float*)d_in[4];
    const float* W2 = (const float*)d_in[5];
    const float* a2 = (const float*)d_in[6];
    const float* b2 = (const float*)d_in[7];
    float* out = (float*)d_out;

    const int* src = el;
    const int* dst = el + N_EDGES;

    cudaFuncSetAttribute(k_gemm1_mma, cudaFuncAttributeMaxDynamicSharedMemorySize, G1_SMEM);
    cudaFuncSetAttribute(k_gemm2_mma, cudaFuncAttributeMaxDynamicSharedMemorySize, G2_SMEM);

    const int TB = 256;
    const int NBLK = (N_NODES + 1023) / 1024;

    // launch index 3 (the ncu-profiled slot) is gemm1
    k_split_x<<<(N_NODES * NFEAT / 8 + TB - 1) / TB, TB>>>(x);          // 0
    k_split_w<<<(F1 * NFEAT + TB - 1) / TB, TB>>>(W1);                  // 1
    k_zero_deg<<<(N_NODES + TB - 1) / TB, TB>>>();                      // 2
    k_gemm1_mma<<<dim3((N_NODES + G1_BM - 1) / G1_BM, F1 / G1_BN), 256, G1_SMEM>>>(); // 3
    k_split_w2<<<(N2PAD * F1 + TB - 1) / TB, TB>>>(W2);                 // 4
    k_count<<<(N_EDGES + TB - 1) / TB, TB>>>(dst);                      // 5
    k_scan_blk<<<NBLK, 256>>>();                                        // 6
    k_scan_top<<<1, 32>>>();                                            // 7
    k_scan_add<<<(N_NODES + TB - 1) / TB, TB>>>();                      // 8
    k_fill<<<(N_EDGES + TB - 1) / TB, TB>>>(src, dst);                  // 9
    k_scores1<<<(N_NODES + 7) / 8, 256>>>(a1);                          // 10
    k_agg1<<<(N_NODES + 7) / 8, 256>>>(b1);                             // 11
    k_gemm2_mma<<<(N_NODES + G2_BM - 1) / G2_BM, 256, G2_SMEM>>>();     // 12
    k_scores2<<<(N_NODES + 7) / 8, 256>>>(a2);                          // 13
    k_agg2<<<(N_NODES + 7) / 8, 256>>>(b2, out);                        // 14
}

// round 9
// speedup vs baseline: 2.1971x; 1.1830x over previous
#include <cuda_runtime.h>
#include <cuda_bf16.h>
#include <cuda_fp16.h>
#include <cstdint>

#define N_NODES 50000
#define N_EDGES 800000
#define NFEAT   512
#define NHID    64
#define NHEAD   8
#define F1      512      // NHEAD*NHID
#define NCLASS  40
#define N2PAD   64
#define NEG     0.2f

// ---------------- scratch ---------------------------------------------------
__device__ __half g_h1h[(size_t)N_NODES * F1];   // fp16 gather copy of h1
__device__ float g_h2[(size_t)N_NODES * NCLASS];
__device__ float g_s1s[N_NODES * NHEAD];
__device__ float g_s1d[N_NODES * NHEAD];
__device__ float g_s2s[N_NODES];
__device__ float g_s2d[N_NODES];
__device__ int   g_deg[N_NODES];
__device__ int   g_off[N_NODES + 1];
__device__ int   g_cur[N_NODES];
__device__ int   g_csr_src[N_EDGES];
__device__ int   g_bsum[64];
__device__ int   g_bpre[64];
// bf16 split operands
__device__ __nv_bfloat16 g_xhi[(size_t)N_NODES * NFEAT];
__device__ __nv_bfloat16 g_xlo[(size_t)N_NODES * NFEAT];
__device__ __nv_bfloat16 g_WThi[F1 * NFEAT];   // [n][k], n = h*64+c
__device__ __nv_bfloat16 g_WTlo[F1 * NFEAT];
__device__ __nv_bfloat16 g_zhi[(size_t)N_NODES * F1];   // layer-2 input, split
__device__ __nv_bfloat16 g_zlo[(size_t)N_NODES * F1];
__device__ __nv_bfloat16 g_W2hi[N2PAD * F1];   // [n][k], n padded to 64
__device__ __nv_bfloat16 g_W2lo[N2PAD * F1];

__device__ __forceinline__ uint32_t smem_u32(const void* p) {
    uint32_t a;
    asm("{ .reg .u64 t; cvta.to.shared.u64 t, %1; cvt.u32.u64 %0, t; }" : "=r"(a) : "l"(p));
    return a;
}

#define LDSM_X4(r0, r1, r2, r3, addr) \
    asm volatile("ldmatrix.sync.aligned.m8n8.x4.shared.b16 {%0,%1,%2,%3}, [%4];" \
                 : "=r"(r0), "=r"(r1), "=r"(r2), "=r"(r3) : "r"(addr))
#define MMA16816(acc, a, b0, b1) \
    asm volatile("mma.sync.aligned.m16n8k16.row.col.f32.bf16.bf16.f32 " \
                 "{%0,%1,%2,%3}, {%4,%5,%6,%7}, {%8,%9}, {%0,%1,%2,%3};" \
                 : "+f"((acc)[0]), "+f"((acc)[1]), "+f"((acc)[2]), "+f"((acc)[3]) \
                 : "r"((a)[0]), "r"((a)[1]), "r"((a)[2]), "r"((a)[3]), "r"(b0), "r"(b1))

// ---------------- CSR construction ------------------------------------------
__global__ void k_zero_deg() {
    int i = blockIdx.x * blockDim.x + threadIdx.x;
    if (i < N_NODES) g_deg[i] = 0;
}
__global__ void k_zero_s1() {
    int i = blockIdx.x * blockDim.x + threadIdx.x;
    if (i < N_NODES * NHEAD) {
        g_s1s[i] = 0.f;
        g_s1d[i] = 0.f;
    }
}
__global__ void k_count(const int* __restrict__ dst) {
    int e = blockIdx.x * blockDim.x + threadIdx.x;
    if (e < N_EDGES) atomicAdd(&g_deg[dst[e]], 1);
}
__global__ __launch_bounds__(256) void k_scan_blk() {
    __shared__ int wsum[8];
    const int blk = blockIdx.x, t = threadIdx.x;
    const int base = blk * 1024 + t * 4;
    int v[4], s = 0;
#pragma unroll
    for (int j = 0; j < 4; j++) {
        int i = base + j;
        v[j] = (i < N_NODES) ? g_deg[i] : 0;
        s += v[j];
    }
    const int lane = t & 31, w = t >> 5;
    int ps = s;
#pragma unroll
    for (int o = 1; o < 32; o <<= 1) {
        int y = __shfl_up_sync(0xffffffffu, ps, o);
        if (lane >= o) ps += y;
    }
    if (lane == 31) wsum[w] = ps;
    __syncthreads();
    if (w == 0) {
        int ws = (lane < 8) ? wsum[lane] : 0;
#pragma unroll
        for (int o = 1; o < 8; o <<= 1) {
            int y = __shfl_up_sync(0xffffffffu, ws, o);
            if (lane >= o) ws += y;
        }
        if (lane < 8) wsum[lane] = ws;
    }
    __syncthreads();
    int run = ps - s + (w > 0 ? wsum[w - 1] : 0);
#pragma unroll
    for (int j = 0; j < 4; j++) {
        int i = base + j;
        if (i < N_NODES) g_off[i] = run;
        run += v[j];
    }
    if (t == 255) g_bsum[blk] = wsum[7];
}
__global__ void k_scan_top() {
    const int lane = threadIdx.x;
    const int nblk = (N_NODES + 1023) / 1024;
    int a = (lane < nblk) ? g_bsum[lane] : 0;
    int b = (lane + 32 < nblk) ? g_bsum[lane + 32] : 0;
    int pa = a;
#pragma unroll
    for (int o = 1; o < 32; o <<= 1) {
        int y = __shfl_up_sync(0xffffffffu, pa, o);
        if (lane >= o) pa += y;
    }
    int tot0 = __shfl_sync(0xffffffffu, pa, 31);
    int pb = b;
#pragma unroll
    for (int o = 1; o < 32; o <<= 1) {
        int y = __shfl_up_sync(0xffffffffu, pb, o);
        if (lane >= o) pb += y;
    }
    if (lane < nblk) g_bpre[lane] = pa - a;
    if (lane + 32 < nblk) g_bpre[lane + 32] = tot0 + pb - b;
}
__global__ void k_scan_add() {
    int i = blockIdx.x * blockDim.x + threadIdx.x;
    if (i < N_NODES) {
        int o = g_off[i] + g_bpre[i >> 10];
        g_off[i] = o;
        g_cur[i] = o;
    }
    if (i == 0) g_off[N_NODES] = N_EDGES;
}
__global__ void k_fill(const int* __restrict__ src, const int* __restrict__ dst) {
    int e = blockIdx.x * blockDim.x + threadIdx.x;
    if (e < N_EDGES) {
        int d = dst[e];
        int p = atomicAdd(&g_cur[d], 1);
        g_csr_src[p] = src[e];
    }
}

// ---------------- bf16 splits ------------------------------------------------
__global__ void k_split_x(const float* __restrict__ x) {
    int i = blockIdx.x * blockDim.x + threadIdx.x;
    const int total = N_NODES * NFEAT / 8;
    if (i >= total) return;
    const float4* p = (const float4*)x + (size_t)i * 2;
    float4 v0 = p[0], v1 = p[1];
    float f[8] = {v0.x, v0.y, v0.z, v0.w, v1.x, v1.y, v1.z, v1.w};
    __nv_bfloat16 hi[8], lo[8];
#pragma unroll
    for (int j = 0; j < 8; j++) {
        hi[j] = __float2bfloat16(f[j]);
        lo[j] = __float2bfloat16(f[j] - __bfloat162float(hi[j]));
    }
    *(uint4*)(g_xhi + (size_t)i * 8) = *(uint4*)hi;
    *(uint4*)(g_xlo + (size_t)i * 8) = *(uint4*)lo;
}
__global__ void k_split_w(const float* __restrict__ W1) {
    int idx = blockIdx.x * blockDim.x + threadIdx.x;
    if (idx >= F1 * NFEAT) return;
    int n = idx >> 9, k = idx & 511;
    int h = n >> 6, c = n & 63;
    float w = W1[((size_t)h * NFEAT + k) * NHID + c];
    __nv_bfloat16 hi = __float2bfloat16(w);
    __nv_bfloat16 lo = __float2bfloat16(w - __bfloat162float(hi));
    g_WThi[(size_t)n * NFEAT + k] = hi;
    g_WTlo[(size_t)n * NFEAT + k] = lo;
}
__global__ void k_split_w2(const float* __restrict__ W2) {
    int idx = blockIdx.x * blockDim.x + threadIdx.x;
    if (idx >= N2PAD * F1) return;
    int n = idx >> 9, k = idx & 511;
    float w = (n < NCLASS) ? W2[(size_t)k * NCLASS + n] : 0.f;
    __nv_bfloat16 hi = __float2bfloat16(w);
    __nv_bfloat16 lo = __float2bfloat16(w - __bfloat162float(hi));
    g_W2hi[(size_t)n * F1 + k] = hi;
    g_W2lo[(size_t)n * F1 + k] = lo;
}

// ---------------- GEMM1 (fused-split HMMA + fused scores) -------------------
#define G1_BM     128
#define G1_BN     128
#define G1_KITER  16                 // 512 / 32
#define G1_ROWB   80
#define G1_REG    10240
#define G1_STAGE  (4 * G1_REG)       // 40960
#define G1_SMEM   (2 * G1_STAGE)     // 81920

__device__ __forceinline__ void g1_prefetch(int kb, uint32_t stage, int bm, int bn, int t) {
    const int k_in = kb * 32;
#pragma unroll
    for (int i = 0; i < 8; i++) {
        int q = t + i * 256;
        int region = q >> 9;          // 0:Ahi 1:Alo 2:Bhi 3:Blo
        int idx = q & 511;
        int row = idx >> 2, c = idx & 3;
        uint32_t dst = stage + region * G1_REG + row * G1_ROWB + c * 16;
        if (region < 2) {
            int grow = bm + row;
            int ok = grow < N_NODES;
            if (!ok) grow = 0;
            const __nv_bfloat16* Asrc = region ? g_xlo : g_xhi;
            const void* srcp = Asrc + (size_t)grow * NFEAT + k_in + c * 8;
            int sz = ok ? 16 : 0;
            asm volatile("cp.async.cg.shared.global [%0], [%1], 16, %2;"
                         :: "r"(dst), "l"(srcp), "r"(sz));
        } else {
            const __nv_bfloat16* Bsrc = (region == 3) ? g_WTlo : g_WThi;
            const void* srcp = Bsrc + (size_t)(bn + row) * NFEAT + k_in + c * 8;
            asm volatile("cp.async.cg.shared.global [%0], [%1], 16;"
                         :: "r"(dst), "l"(srcp));
        }
    }
}

__global__ __launch_bounds__(256, 2) void k_gemm1_mma(const float* __restrict__ a1) {
    extern __shared__ char dyn[];
    const uint32_t sbase = smem_u32(dyn);
    const int t    = threadIdx.x;
    const int wid  = t >> 5;
    const int lane = t & 31;
    const int bm   = blockIdx.x * G1_BM;
    const int bn   = blockIdx.y * G1_BN;
    const int mw   = (wid >> 2) * 64;
    const int nw   = (wid & 3) * 32;

    float acc[4][4][4];
#pragma unroll
    for (int mt = 0; mt < 4; mt++)
#pragma unroll
        for (int nt = 0; nt < 4; nt++)
#pragma unroll
            for (int j = 0; j < 4; j++) acc[mt][nt][j] = 0.f;

    g1_prefetch(0, sbase, bm, bn, t);
    asm volatile("cp.async.commit_group;");
    g1_prefetch(1, sbase + G1_STAGE, bm, bn, t);
    asm volatile("cp.async.commit_group;");

    const uint32_t a_off = (mw + (lane & 15)) * G1_ROWB + ((lane >> 4) * 16);
    const uint32_t b_off = (nw + (lane & 7) + ((lane >> 4) << 3)) * G1_ROWB + (((lane >> 3) & 1) * 16);

    for (int kb = 0; kb < G1_KITER; kb++) {
        asm volatile("cp.async.wait_group 1;");
        __syncthreads();
        const uint32_t stage = sbase + (kb & 1) * G1_STAGE;

#pragma unroll
        for (int ks = 0; ks < 2; ks++) {
            uint32_t ahi[4][4], alo[4][4];
#pragma unroll
            for (int mt = 0; mt < 4; mt++) {
                uint32_t ad = stage + a_off + mt * (16 * G1_ROWB) + ks * 32;
                LDSM_X4(ahi[mt][0], ahi[mt][1], ahi[mt][2], ahi[mt][3], ad);
                LDSM_X4(alo[mt][0], alo[mt][1], alo[mt][2], alo[mt][3], ad + G1_REG);
            }
            uint32_t b[2][4];
#pragma unroll
            for (int np = 0; np < 2; np++) {
                uint32_t bd = stage + 2 * G1_REG + b_off + np * (16 * G1_ROWB) + ks * 32;
                LDSM_X4(b[np][0], b[np][1], b[np][2], b[np][3], bd);
            }
#pragma unroll
            for (int mt = 0; mt < 4; mt++)
#pragma unroll
                for (int nt = 0; nt < 4; nt++) {
                    const uint32_t b0 = b[nt >> 1][(nt & 1) * 2];
                    const uint32_t b1 = b[nt >> 1][(nt & 1) * 2 + 1];
                    MMA16816(acc[mt][nt], ahi[mt], b0, b1);
                    MMA16816(acc[mt][nt], alo[mt], b0, b1);
                }
#pragma unroll
            for (int np = 0; np < 2; np++) {
                uint32_t bd = stage + 3 * G1_REG + b_off + np * (16 * G1_ROWB) + ks * 32;
                LDSM_X4(b[np][0], b[np][1], b[np][2], b[np][3], bd);
            }
#pragma unroll
            for (int mt = 0; mt < 4; mt++)
#pragma unroll
                for (int nt = 0; nt < 4; nt++) {
                    const uint32_t b0 = b[nt >> 1][(nt & 1) * 2];
                    const uint32_t b1 = b[nt >> 1][(nt & 1) * 2 + 1];
                    MMA16816(acc[mt][nt], ahi[mt], b0, b1);
                }
        }
        __syncthreads();
        if (kb + 2 < G1_KITER)
            g1_prefetch(kb + 2, stage, bm, bn, t);
        asm volatile("cp.async.commit_group;");
    }

    // epilogue: fp16 h1h + fused layer-1 attention scores.
    // This warp's 32-col span lies inside one head hw.
    const int r_base = bm + mw + (lane >> 2);
    const int hw = (bn + nw) >> 6;                 // head index
    const int co0 = ((bn + nw) & 63) + (lane & 3) * 2;  // col-within-head base
#pragma unroll
    for (int mt = 0; mt < 4; mt++) {
#pragma unroll
        for (int nt = 0; nt < 4; nt++) {
            int r0 = r_base + mt * 16;
            int cc = bn + nw + (lane & 3) * 2 + nt * 8;
            if (r0 < N_NODES)
                *(__half2*)(g_h1h + (size_t)r0 * F1 + cc) = __floats2half2_rn(acc[mt][nt][0], acc[mt][nt][1]);
            if (r0 + 8 < N_NODES)
                *(__half2*)(g_h1h + (size_t)(r0 + 8) * F1 + cc) = __floats2half2_rn(acc[mt][nt][2], acc[mt][nt][3]);
        }
        // scores: partial dot of this thread's 8 cols x 2 rows with a1
        float s0 = 0.f, d0 = 0.f, s1 = 0.f, d1 = 0.f;
#pragma unroll
        for (int nt = 0; nt < 4; nt++) {
#pragma unroll
            for (int je = 0; je < 2; je++) {
                int co = co0 + nt * 8 + je;
                float a_s = a1[hw * 128 + co];
                float a_d = a1[hw * 128 + 64 + co];
                s0 += acc[mt][nt][je] * a_s;
                d0 += acc[mt][nt][je] * a_d;
                s1 += acc[mt][nt][2 + je] * a_s;
                d1 += acc[mt][nt][2 + je] * a_d;
            }
        }
        // reduce across the lane-quad (same rows, different cols)
        s0 += __shfl_xor_sync(0xffffffffu, s0, 1); s0 += __shfl_xor_sync(0xffffffffu, s0, 2);
        d0 += __shfl_xor_sync(0xffffffffu, d0, 1); d0 += __shfl_xor_sync(0xffffffffu, d0, 2);
        s1 += __shfl_xor_sync(0xffffffffu, s1, 1); s1 += __shfl_xor_sync(0xffffffffu, s1, 2);
        d1 += __shfl_xor_sync(0xffffffffu, d1, 1); d1 += __shfl_xor_sync(0xffffffffu, d1, 2);
        if ((lane & 3) == 0) {
            int r0 = r_base + mt * 16;
            if (r0 < N_NODES) {
                atomicAdd(&g_s1s[r0 * NHEAD + hw], s0);
                atomicAdd(&g_s1d[r0 * NHEAD + hw], d0);
            }
            if (r0 + 8 < N_NODES) {
                atomicAdd(&g_s1s[(r0 + 8) * NHEAD + hw], s1);
                atomicAdd(&g_s1d[(r0 + 8) * NHEAD + hw], d1);
            }
        }
    }
}

// ---------------- GEMM2 (fused-split HMMA): h2 = z @ W2 ---------------------
#define G2_BM     128
#define G2_KITER  16
#define G2_AREG   10240
#define G2_BREG   5120
#define G2_STAGE  (2 * G2_AREG + 2 * G2_BREG)   // 30720
#define G2_SMEM   (2 * G2_STAGE)                // 61440

__device__ __forceinline__ void g2_prefetch(int kb, uint32_t stage, int bm, int t) {
    const int k_in = kb * 32;
#pragma unroll
    for (int i = 0; i < 6; i++) {
        int q = t + i * 256;
        if (q < 1024) {
            int region = q >> 9;
            int idx = q & 511;
            int row = idx >> 2, c = idx & 3;
            uint32_t dst = stage + region * G2_AREG + row * G1_ROWB + c * 16;
            int grow = bm + row;
            int ok = grow < N_NODES;
            if (!ok) grow = 0;
            const __nv_bfloat16* Asrc = region ? g_zlo : g_zhi;
            const void* srcp = Asrc + (size_t)grow * F1 + k_in + c * 8;
            int sz = ok ? 16 : 0;
            asm volatile("cp.async.cg.shared.global [%0], [%1], 16, %2;"
                         :: "r"(dst), "l"(srcp), "r"(sz));
        } else {
            int qb = q - 1024;
            int region = qb >> 8;
            int idx = qb & 255;
            int row = idx >> 2, c = idx & 3;
            uint32_t dst = stage + 2 * G2_AREG + region * G2_BREG + row * G1_ROWB + c * 16;
            const __nv_bfloat16* Bsrc = region ? g_W2lo : g_W2hi;
            const void* srcp = Bsrc + (size_t)row * F1 + k_in + c * 8;
            asm volatile("cp.async.cg.shared.global [%0], [%1], 16;"
                         :: "r"(dst), "l"(srcp));
        }
    }
}

__global__ __launch_bounds__(256, 2) void k_gemm2_mma() {
    extern __shared__ char dyn[];
    const uint32_t sbase = smem_u32(dyn);
    const int t    = threadIdx.x;
    const int wid  = t >> 5;
    const int lane = t & 31;
    const int bm   = blockIdx.x * G2_BM;
    const int mw   = (wid >> 1) * 32;
    const int nw   = (wid & 1) * 32;

    float acc[2][4][4];
#pragma unroll
    for (int mt = 0; mt < 2; mt++)
#pragma unroll
        for (int nt = 0; nt < 4; nt++)
#pragma unroll
            for (int j = 0; j < 4; j++) acc[mt][nt][j] = 0.f;

    g2_prefetch(0, sbase, bm, t);
    asm volatile("cp.async.commit_group;");
    g2_prefetch(1, sbase + G2_STAGE, bm, t);
    asm volatile("cp.async.commit_group;");

    const uint32_t a_off = (mw + (lane & 15)) * G1_ROWB + ((lane >> 4) * 16);
    const uint32_t b_off = (nw + (lane & 7) + ((lane >> 4) << 3)) * G1_ROWB + (((lane >> 3) & 1) * 16);

    for (int kb = 0; kb < G2_KITER; kb++) {
        asm volatile("cp.async.wait_group 1;");
        __syncthreads();
        const uint32_t stage = sbase + (kb & 1) * G2_STAGE;

#pragma unroll
        for (int ks = 0; ks < 2; ks++) {
            uint32_t ahi[2][4], alo[2][4];
#pragma unroll
            for (int mt = 0; mt < 2; mt++) {
                uint32_t ad = stage + a_off + mt * (16 * G1_ROWB) + ks * 32;
                LDSM_X4(ahi[mt][0], ahi[mt][1], ahi[mt][2], ahi[mt][3], ad);
                LDSM_X4(alo[mt][0], alo[mt][1], alo[mt][2], alo[mt][3], ad + G2_AREG);
            }
            uint32_t b[2][4];
#pragma unroll
            for (int np = 0; np < 2; np++) {
                uint32_t bd = stage + 2 * G2_AREG + b_off + np * (16 * G1_ROWB) + ks * 32;
                LDSM_X4(b[np][0], b[np][1], b[np][2], b[np][3], bd);
            }
#pragma unroll
            for (int mt = 0; mt < 2; mt++)
#pragma unroll
                for (int nt = 0; nt < 4; nt++) {
                    const uint32_t b0 = b[nt >> 1][(nt & 1) * 2];
                    const uint32_t b1 = b[nt >> 1][(nt & 1) * 2 + 1];
                    MMA16816(acc[mt][nt], ahi[mt], b0, b1);
                    MMA16816(acc[mt][nt], alo[mt], b0, b1);
                }
#pragma unroll
            for (int np = 0; np < 2; np++) {
                uint32_t bd = stage + 2 * G2_AREG + G2_BREG + b_off + np * (16 * G1_ROWB) + ks * 32;
                LDSM_X4(b[np][0], b[np][1], b[np][2], b[np][3], bd);
            }
#pragma unroll
            for (int mt = 0; mt < 2; mt++)
#pragma unroll
                for (int nt = 0; nt < 4; nt++) {
                    const uint32_t b0 = b[nt >> 1][(nt & 1) * 2];
                    const uint32_t b1 = b[nt >> 1][(nt & 1) * 2 + 1];
                    MMA16816(acc[mt][nt], ahi[mt], b0, b1);
                }
        }
        __syncthreads();
        if (kb + 2 < G2_KITER)
            g2_prefetch(kb + 2, stage, bm, t);
        asm volatile("cp.async.commit_group;");
    }

    const int r_base = bm + mw + (lane >> 2);
    const int c_base = nw + (lane & 3) * 2;
#pragma unroll
    for (int mt = 0; mt < 2; mt++) {
#pragma unroll
        for (int nt = 0; nt < 4; nt++) {
            int r0 = r_base + mt * 16;
            int cc = c_base + nt * 8;
            if (cc < NCLASS) {
                if (r0 < N_NODES)
                    *(float2*)(g_h2 + (size_t)r0 * NCLASS + cc) = make_float2(acc[mt][nt][0], acc[mt][nt][1]);
                if (r0 + 8 < N_NODES)
                    *(float2*)(g_h2 + (size_t)(r0 + 8) * NCLASS + cc) = make_float2(acc[mt][nt][2], acc[mt][nt][3]);
            }
        }
    }
}

__device__ __forceinline__ float lrelu(float x) { return x > 0.f ? x : NEG * x; }

// ---------------- layer-1 softmax-aggregate (fp16 gather, split bf16 out) ---
__global__ __launch_bounds__(256) void k_agg1(const float* __restrict__ b1) {
    int n    = (blockIdx.x * blockDim.x + threadIdx.x) >> 5;
    int lane = threadIdx.x & 31;
    if (n >= N_NODES) return;
    const int beg = g_off[n], end = g_off[n + 1];

    const int h  = lane & 7;
    const int es = lane >> 3;
    const float sdh = g_s1d[n * NHEAD + h];

    float m = -1e30f;
    for (int i = beg + es; i < end; i += 4) {
        int s = g_csr_src[i];
        float e = lrelu(g_s1s[s * NHEAD + h] + sdh);
        m = fmaxf(m, e);
    }
    m = fmaxf(m, __shfl_xor_sync(0xffffffffu, m, 8));
    m = fmaxf(m, __shfl_xor_sync(0xffffffffu, m, 16));

    float den = 0.f;
    for (int i = beg + es; i < end; i += 4) {
        int s = g_csr_src[i];
        float e = lrelu(g_s1s[s * NHEAD + h] + sdh);
        den += __expf(e - m);
    }
    den += __shfl_xor_sync(0xffffffffu, den, 8);
    den += __shfl_xor_sync(0xffffffffu, den, 16);
    den = fmaxf(den, 1e-16f);

    float acc[16];
#pragma unroll
    for (int j = 0; j < 16; j++) acc[j] = 0.f;
    const int hl = lane >> 2;

    for (int i = beg; i < end; i++) {
        int s = g_csr_src[i];
        float alpha = 0.f;
        if (lane < 8) {
            float e = lrelu(g_s1s[s * NHEAD + lane] + sdh);
            alpha = __expf(e - m) / den;
        }
        alpha = __shfl_sync(0xffffffffu, alpha, hl);
        const uint4* hp = (const uint4*)(g_h1h + (size_t)s * F1 + lane * 16);
        uint4 q0 = hp[0];
        uint4 q1 = hp[1];
        float2 f;
        f = __half22float2(*(__half2*)&q0.x); acc[0] += alpha * f.x; acc[1] += alpha * f.y;
        f = __half22float2(*(__half2*)&q0.y); acc[2] += alpha * f.x; acc[3] += alpha * f.y;
        f = __half22float2(*(__half2*)&q0.z); acc[4] += alpha * f.x; acc[5] += alpha * f.y;
        f = __half22float2(*(__half2*)&q0.w); acc[6] += alpha * f.x; acc[7] += alpha * f.y;
        f = __half22float2(*(__half2*)&q1.x); acc[8] += alpha * f.x; acc[9] += alpha * f.y;
        f = __half22float2(*(__half2*)&q1.y); acc[10] += alpha * f.x; acc[11] += alpha * f.y;
        f = __half22float2(*(__half2*)&q1.z); acc[12] += alpha * f.x; acc[13] += alpha * f.y;
        f = __half22float2(*(__half2*)&q1.w); acc[14] += alpha * f.x; acc[15] += alpha * f.y;
    }

    const float4* bp = (const float4*)(b1 + lane * 16);
#pragma unroll
    for (int j = 0; j < 4; j++) {
        float4 b = bp[j];
        float v[4];
        v[0] = acc[j * 4 + 0] + b.x;
        v[1] = acc[j * 4 + 1] + b.y;
        v[2] = acc[j * 4 + 2] + b.z;
        v[3] = acc[j * 4 + 3] + b.w;
        __nv_bfloat16 hi[4], lo[4];
#pragma unroll
        for (int q = 0; q < 4; q++) {
            float e = v[q] > 0.f ? v[q] : expm1f(v[q]);
            hi[q] = __float2bfloat16(e);
            lo[q] = __float2bfloat16(e - __bfloat162float(hi[q]));
        }
        *(uint2*)(g_zhi + (size_t)n * F1 + lane * 16 + j * 4) = *(uint2*)hi;
        *(uint2*)(g_zlo + (size_t)n * F1 + lane * 16 + j * 4) = *(uint2*)lo;
    }
}

// ---------------- per-node attention scores, layer 2 ------------------------
__global__ void k_scores2(const float* __restrict__ a2) {
    int gw   = (blockIdx.x * blockDim.x + threadIdx.x) >> 5;
    int lane = threadIdx.x & 31;
    if (gw >= N_NODES) return;
    float v0 = g_h2[(size_t)gw * NCLASS + lane];
    float ss = v0 * a2[lane];
    float sd = v0 * a2[NCLASS + lane];
    if (lane < 8) {
        float v1 = g_h2[(size_t)gw * NCLASS + 32 + lane];
        ss += v1 * a2[32 + lane];
        sd += v1 * a2[NCLASS + 32 + lane];
    }
#pragma unroll
    for (int off = 16; off > 0; off >>= 1) {
        ss += __shfl_xor_sync(0xffffffffu, ss, off);
        sd += __shfl_xor_sync(0xffffffffu, sd, off);
    }
    if (lane == 0) {
        g_s2s[gw] = ss;
        g_s2d[gw] = sd;
    }
}

// ---------------- layer-2 aggregate + bias + log_softmax --------------------
__global__ __launch_bounds__(256) void k_agg2(const float* __restrict__ b2,
                                              float* __restrict__ out) {
    int n    = (blockIdx.x * blockDim.x + threadIdx.x) >> 5;
    int lane = threadIdx.x & 31;
    if (n >= N_NODES) return;
    const int beg = g_off[n], end = g_off[n + 1];
    const float sdn = g_s2d[n];

    float m = -1e30f;
    for (int i = beg + lane; i < end; i += 32) {
        int s = g_csr_src[i];
        m = fmaxf(m, lrelu(g_s2s[s] + sdn));
    }
#pragma unroll
    for (int off = 16; off > 0; off >>= 1)
        m = fmaxf(m, __shfl_xor_sync(0xffffffffu, m, off));

    float den = 0.f;
    for (int i = beg + lane; i < end; i += 32) {
        int s = g_csr_src[i];
        den += __expf(lrelu(g_s2s[s] + sdn) - m);
    }
#pragma unroll
    for (int off = 16; off > 0; off >>= 1)
        den += __shfl_xor_sync(0xffffffffu, den, off);
    den = fmaxf(den, 1e-16f);

    float acc0 = 0.f, acc1 = 0.f;
    for (int i = beg; i < end; i++) {
        int s = g_csr_src[i];
        float e = lrelu(g_s2s[s] + sdn);
        float alpha = __expf(e - m) / den;
        acc0 += alpha * g_h2[(size_t)s * NCLASS + lane];
        if (lane < 8) acc1 += alpha * g_h2[(size_t)s * NCLASS + 32 + lane];
    }

    float v0 = acc0 + b2[lane];
    float v1 = (lane < 8) ? (acc1 + b2[32 + lane]) : -1e30f;

    float mx = fmaxf(v0, v1);
#pragma unroll
    for (int off = 16; off > 0; off >>= 1)
        mx = fmaxf(mx, __shfl_xor_sync(0xffffffffu, mx, off));
    float se = __expf(v0 - mx) + ((lane < 8) ? __expf(v1 - mx) : 0.f);
#pragma unroll
    for (int off = 16; off > 0; off >>= 1)
        se += __shfl_xor_sync(0xffffffffu, se, off);
    float ls = logf(se);

    out[(size_t)n * NCLASS + lane] = v0 - mx - ls;
    if (lane < 8) out[(size_t)n * NCLASS + 32 + lane] = v1 - mx - ls;
}

// ---------------- launch -----------------------------------------------------
extern "C" void kernel_launch(void* const* d_in, const int* in_sizes, int n_in,
                              void* d_out, int out_size) {
    const float* x  = (const float*)d_in[0];
    const int*   el = (const int*)d_in[1];
    const float* W1 = (const float*)d_in[2];
    const float* a1 = (const float*)d_in[3];
    const float* b1 = (const float*)d_in[4];
    const float* W2 = (const float*)d_in[5];
    const float* a2 = (const float*)d_in[6];
    const float* b2 = (const float*)d_in[7];
    float* out = (float*)d_out;

    const int* src = el;
    const int* dst = el + N_EDGES;

    // one-time host-side resources (no device allocation)
    static cudaStream_t s2 = nullptr;
    static cudaEvent_t ev_fork = nullptr, ev_join = nullptr;
    if (!s2) {
        cudaStreamCreateWithFlags(&s2, cudaStreamNonBlocking);
        cudaEventCreateWithFlags(&ev_fork, cudaEventDisableTiming);
        cudaEventCreateWithFlags(&ev_join, cudaEventDisableTiming);
        cudaFuncSetAttribute(k_gemm1_mma, cudaFuncAttributeMaxDynamicSharedMemorySize, G1_SMEM);
        cudaFuncSetAttribute(k_gemm2_mma, cudaFuncAttributeMaxDynamicSharedMemorySize, G2_SMEM);
    }

    const int TB = 256;
    const int NBLK = (N_NODES + 1023) / 1024;

    // main stream: split + zero + gemm1 (gemm1 = submission index 3 for ncu)
    k_split_x<<<(N_NODES * NFEAT / 8 + TB - 1) / TB, TB>>>(x);                    // 0
    k_split_w<<<(F1 * NFEAT + TB - 1) / TB, TB>>>(W1);                            // 1
    k_zero_s1<<<(N_NODES * NHEAD + TB - 1) / TB, TB>>>();                         // 2
    k_gemm1_mma<<<dim3((N_NODES + G1_BM - 1) / G1_BM, F1 / G1_BN), 256, G1_SMEM>>>(a1); // 3
    cudaEventRecord(ev_fork, 0);

    // side stream: CSR build + W2 split (independent of gemm1)
    cudaStreamWaitEvent(s2, ev_fork, 0);
    k_zero_deg<<<(N_NODES + TB - 1) / TB, TB, 0, s2>>>();
    k_count<<<(N_EDGES + TB - 1) / TB, TB, 0, s2>>>(dst);
    k_scan_blk<<<NBLK, 256, 0, s2>>>();
    k_scan_top<<<1, 32, 0, s2>>>();
    k_scan_add<<<(N_NODES + TB - 1) / TB, TB, 0, s2>>>();
    k_fill<<<(N_EDGES + TB - 1) / TB, TB, 0, s2>>>(src, dst);
    k_split_w2<<<(N2PAD * F1 + TB - 1) / TB, TB, 0, s2>>>(W2);
    cudaEventRecord(ev_join, s2);

    // main stream rejoins, then the dependent chain
    cudaStreamWaitEvent(0, ev_join, 0);
    k_agg1<<<(N_NODES + 7) / 8, 256>>>(b1);
    k_gemm2_mma<<<(N_NODES + G2_BM - 1) / G2_BM, 256, G2_SMEM>>>();
    k_scores2<<<(N_NODES + 7) / 8, 256>>>(a2);
    k_agg2<<<(N_NODES + 7) / 8, 256>>>(b2, out);
}